// round 9
// baseline (speedup 1.0000x reference)
#include <cuda_runtime.h>
#include <cuda_bf16.h>
#include <math.h>
#include <stdint.h>

// ---------------- problem constants ----------------
#define BB 4
#define TT 1024
#define EE 768
#define HH 8
#define HS 96
#define LL 8
#define VV 32000
#define FF 3072            // 4*E
#define MM (BB*TT)         // 4096 rows
#define E3 (3*EE)          // 2304 (split-K for E)
#define F3 (3*FF)          // 9216 (split-K for 4E)

typedef __nv_bfloat16 bf16;

// ---------------- scratch (device globals; no allocation allowed) ----------------
__device__ __align__(256) float g_x   [(size_t)MM*EE];
__device__ __align__(256) bf16  g_xn2 [(size_t)MM*E3];
__device__ __align__(256) bf16  g_qkv2[(size_t)MM*3*E3];
__device__ __align__(256) bf16  g_att2[(size_t)MM*E3];
__device__ __align__(256) bf16  g_h42 [(size_t)MM*F3];

// weights, B-layout [K3 rows][N cols], K-segments [hi; lo; hi]
__device__ __align__(256) bf16  g_wqkv2[(size_t)LL*E3*E3];
__device__ __align__(256) bf16  g_wo2  [(size_t)LL*E3*EE];
__device__ __align__(256) bf16  g_w12  [(size_t)LL*E3*FF];
__device__ __align__(256) bf16  g_w22  [(size_t)LL*F3*EE];
__device__ __align__(256) bf16  g_tok2 [(size_t)E3*VV];

__device__ __align__(256) float g_logits_scratch[(size_t)MM*VV];

// ---------------- helpers ----------------
__device__ __forceinline__ void split2(float v, bf16& hi, bf16& lo) {
    hi = __float2bfloat16(v);
    lo = __float2bfloat16(v - __bfloat162float(hi));
}
__device__ __forceinline__ uint32_t pack2(bf16 a, bf16 b) {
    uint16_t x = *(uint16_t*)&a, y = *(uint16_t*)&b;
    return (uint32_t)x | ((uint32_t)y << 16);
}
__device__ __forceinline__ void cp16(void* dst_smem, const void* src_gmem) {
    uint32_t s = (uint32_t)__cvta_generic_to_shared(dst_smem);
    asm volatile("cp.async.cg.shared.global [%0], [%1], 16;\n" :: "r"(s), "l"(src_gmem));
}
__device__ __forceinline__ void cp_commit() { asm volatile("cp.async.commit_group;\n" ::: "memory"); }
__device__ __forceinline__ void cp_wait1()  { asm volatile("cp.async.wait_group 1;\n" ::: "memory"); }

__device__ __forceinline__ void ldmA4(uint32_t* a, const void* p) {
    uint32_t s = (uint32_t)__cvta_generic_to_shared(p);
    asm volatile("ldmatrix.sync.aligned.m8n8.x4.shared.b16 {%0,%1,%2,%3}, [%4];"
                 : "=r"(a[0]), "=r"(a[1]), "=r"(a[2]), "=r"(a[3]) : "r"(s));
}
__device__ __forceinline__ void ldmB4t(uint32_t* b, const void* p) {
    uint32_t s = (uint32_t)__cvta_generic_to_shared(p);
    asm volatile("ldmatrix.sync.aligned.m8n8.x4.trans.shared.b16 {%0,%1,%2,%3}, [%4];"
                 : "=r"(b[0]), "=r"(b[1]), "=r"(b[2]), "=r"(b[3]) : "r"(s));
}
__device__ __forceinline__ void mma16816(float* c, const uint32_t* a, const uint32_t* b) {
    asm volatile(
        "mma.sync.aligned.m16n8k16.row.col.f32.bf16.bf16.f32 "
        "{%0,%1,%2,%3},{%4,%5,%6,%7},{%8,%9},{%0,%1,%2,%3};"
        : "+f"(c[0]), "+f"(c[1]), "+f"(c[2]), "+f"(c[3])
        : "r"(a[0]), "r"(a[1]), "r"(a[2]), "r"(a[3]), "r"(b[0]), "r"(b[1]));
}

// ---------------- ONE batched weight conversion (all layers, all 6 tensors) -------------
// grid: (9216, 48). blockIdx.y = layer*6 + segment. W[K,N] fp32 -> B rows [hi; lo; hi].
__global__ void convert_all_kernel(const float* __restrict__ Wq, const float* __restrict__ Wk,
                                   const float* __restrict__ Wv, const float* __restrict__ Wo,
                                   const float* __restrict__ W1, const float* __restrict__ W2)
{
    const int l = blockIdx.y / 6, seg = blockIdx.y % 6;
    const float* W; bf16* out; int K, N, pitch, colOff;
    switch (seg) {
        case 0: W = Wq + (size_t)l*EE*EE; out = g_wqkv2 + (size_t)l*E3*E3; K=EE; N=EE; pitch=E3; colOff=0;    break;
        case 1: W = Wk + (size_t)l*EE*EE; out = g_wqkv2 + (size_t)l*E3*E3; K=EE; N=EE; pitch=E3; colOff=EE;   break;
        case 2: W = Wv + (size_t)l*EE*EE; out = g_wqkv2 + (size_t)l*E3*E3; K=EE; N=EE; pitch=E3; colOff=2*EE; break;
        case 3: W = Wo + (size_t)l*EE*EE; out = g_wo2   + (size_t)l*E3*EE; K=EE; N=EE; pitch=EE; colOff=0;    break;
        case 4: W = W1 + (size_t)l*EE*FF; out = g_w12   + (size_t)l*E3*FF; K=EE; N=FF; pitch=FF; colOff=0;    break;
        default:W = W2 + (size_t)l*FF*EE; out = g_w22   + (size_t)l*F3*EE; K=FF; N=EE; pitch=EE; colOff=0;    break;
    }
    int i = blockIdx.x * 256 + threadIdx.x;
    if (i >= K * N) return;
    int k = i / N, n = i % N;
    float v = W[i];
    bf16 hi, lo; split2(v, hi, lo);
    out[(size_t)k * pitch + colOff + n]           = hi;
    out[(size_t)(K + k) * pitch + colOff + n]     = lo;
    out[(size_t)(2 * K + k) * pitch + colOff + n] = hi;
}

// Contract: A segments [hi | hi | lo], B rows [hi; lo; hi]
//   seg0: Ahi*Bhi, seg1: Ahi*Blo, seg2: Alo*Bhi   (lo*lo dropped, ~2^-18)

// ---------------- tok transpose + split: out[3E, V] from tok[V, E] (B-side) ----------------
__global__ void convert_tok_kernel(const float* __restrict__ tok, bf16* __restrict__ out)
{
    __shared__ float t[32][33];
    int k0 = blockIdx.x * 32, n0 = blockIdx.y * 32;
    int tx = threadIdx.x, ty = threadIdx.y;
    t[ty][tx] = tok[(size_t)(n0 + ty) * EE + k0 + tx];
    __syncthreads();
    float v = t[tx][ty];
    bf16 hi, lo; split2(v, hi, lo);
    size_t k = k0 + ty, n = n0 + tx;
    out[k * VV + n]              = hi;
    out[(EE + k) * VV + n]       = lo;
    out[(2*EE + k) * VV + n]     = hi;
}

// ---------------- embedding ----------------
__global__ void embed_kernel(const int* __restrict__ idx,
                             const float* __restrict__ tok,
                             const float* __restrict__ pos,
                             float* __restrict__ x)
{
    size_t i = (size_t)blockIdx.x * blockDim.x + threadIdx.x;
    if (i >= (size_t)MM * EE) return;
    int e  = (int)(i % EE);
    int bt = (int)(i / EE);
    int t  = bt % TT;
    x[i] = tok[(size_t)idx[bt] * EE + e] + pos[(size_t)t * EE + e];
}

// ---------------- layernorm -> A-side split bf16 [row, 3E]: [hi | hi | lo] ----------------
__global__ void ln_split_kernel(const float* __restrict__ x,
                                const float* __restrict__ g,
                                const float* __restrict__ b,
                                bf16* __restrict__ out)
{
    int row = blockIdx.x;
    int tid = threadIdx.x;  // 256
    const float* xr = x + (size_t)row * EE;
    float s = 0.f, s2 = 0.f;
    for (int e = tid; e < EE; e += 256) { float v = xr[e]; s += v; s2 += v * v; }
    __shared__ float r1[256], r2[256];
    r1[tid] = s; r2[tid] = s2; __syncthreads();
    for (int o = 128; o > 0; o >>= 1) {
        if (tid < o) { r1[tid] += r1[tid + o]; r2[tid] += r2[tid + o]; }
        __syncthreads();
    }
    float mean = r1[0] * (1.f / EE);
    float var  = r2[0] * (1.f / EE) - mean * mean;
    float inv  = rsqrtf(var + 1e-5f);
    bf16* orow = out + (size_t)row * E3;
    for (int e = tid; e < EE; e += 256) {
        float v = (xr[e] - mean) * inv * g[e] + b[e];
        bf16 hi, lo; split2(v, hi, lo);
        orow[e] = hi; orow[EE + e] = hi; orow[2*EE + e] = lo;
    }
}

// ---------------- tensor-core GEMM: C[M,N] = A[M,K2] @ B[K2,N] ----------------
// Persistent CTAs (col-major tile order). Block tile 128 x (32*NFRAG); warp tile 64 x (8*NFRAG).
// NFRAG=4 -> TN=128, 2 CTAs/SM, smem 73728.  NFRAG=8 -> TN=256, 1 CTA/SM, smem 106496.
template<int NFRAG, bool GELU, bool SPLIT>
__global__ void __launch_bounds__(256, (NFRAG == 4) ? 2 : 1)
mma_gemm(const bf16* __restrict__ A, const bf16* __restrict__ B,
         const float* __restrict__ bias, const float* __restrict__ res,
         void* __restrict__ Cv, int M, int N, int K2)
{
    constexpr int TN = 32 * NFRAG;
    constexpr int BP = TN + 16;          // B smem pitch
    extern __shared__ char dynsm[];
    bf16* As = (bf16*)dynsm;             // [2][128*72]
    bf16* Bs = (bf16*)dynsm + 18432;     // [2][64*BP]

    const int tid  = threadIdx.x;
    const int lane = tid & 31;
    const int warp = tid >> 5;
    const int wm   = warp & 1;           // 64-row slab
    const int wn   = warp >> 1;          // (8*NFRAG)-col slab

    float acc[4][NFRAG][4];

    const int nRowT = M >> 7;
    const int nColT = N / TN;
    const int nTiles = nRowT * nColT;
    const int ntk = K2 >> 6;

    for (int tile = blockIdx.x; tile < nTiles; tile += gridDim.x) {
        const int col0 = (tile / nRowT) * TN;
        const int row0 = (tile % nRowT) * 128;

#pragma unroll
        for (int i = 0; i < 4; i++)
#pragma unroll
            for (int j = 0; j < NFRAG; j++)
#pragma unroll
                for (int r = 0; r < 4; r++) acc[i][j][r] = 0.f;

        auto load_tile = [&](int s, int k0) {
#pragma unroll
            for (int i = 0; i < 4; i++) {
                int idx = tid + i * 256;
                int r = idx >> 3, c = (idx & 7) * 8;
                cp16(&As[s * 9216 + r * 72 + c], &A[(size_t)(row0 + r) * K2 + k0 + c]);
            }
            constexpr int LD = TN / 8;       // 8-col chunks per row
            // B tile: 64 rows * LD chunks = 8*TN ops -> NFRAG iterations of 256 threads
#pragma unroll
            for (int i = 0; i < NFRAG; i++) {
                int idx = tid + i * 256;
                int r = idx / LD, c = (idx % LD) * 8;
                cp16(&Bs[s * 64 * BP + r * BP + c], &B[(size_t)(k0 + r) * N + col0 + c]);
            }
        };

        __syncthreads();   // protect smem from previous tile's consumers
        load_tile(0, 0);
        cp_commit();

        for (int t = 0; t < ntk; t++) {
            if (t + 1 < ntk) load_tile((t + 1) & 1, (t + 1) * 64);
            cp_commit();
            cp_wait1();
            __syncthreads();
            const int s = t & 1;

#pragma unroll
            for (int kk = 0; kk < 64; kk += 16) {
                uint32_t a[4][4], b[NFRAG / 2][4];
#pragma unroll
                for (int mi = 0; mi < 4; mi++)
                    ldmA4(a[mi], &As[s * 9216 + (wm * 64 + mi * 16 + (lane & 15)) * 72 + kk + (lane >> 4) * 8]);
#pragma unroll
                for (int nj = 0; nj < NFRAG / 2; nj++)
                    ldmB4t(b[nj], &Bs[s * 64 * BP + (kk + (lane & 15)) * BP + wn * (8 * NFRAG) + nj * 16 + (lane >> 4) * 8]);
#pragma unroll
                for (int mi = 0; mi < 4; mi++)
#pragma unroll
                    for (int nj = 0; nj < NFRAG / 2; nj++) {
                        mma16816(acc[mi][2 * nj],     a[mi], b[nj]);
                        mma16816(acc[mi][2 * nj + 1], a[mi], b[nj] + 2);
                    }
            }
            __syncthreads();
        }

        // ---- epilogue ----
        const int gid = lane >> 2, tig = lane & 3;
#pragma unroll
        for (int mi = 0; mi < 4; mi++) {
#pragma unroll
            for (int ni = 0; ni < NFRAG; ni++) {
                int gr = row0 + wm * 64 + mi * 16 + gid;
                int gc = col0 + wn * (8 * NFRAG) + ni * 8 + tig * 2;
#pragma unroll
                for (int half = 0; half < 2; half++) {
                    int r = gr + half * 8;
#pragma unroll
                    for (int cc = 0; cc < 2; cc++) {
                        float c = acc[mi][ni][half * 2 + cc];
                        int col = gc + cc;
                        if (bias) c += bias[col];
                        if (GELU) c = 0.5f * c * (1.f + erff(c * 0.70710678118654752f));
                        if (SPLIT) {
                            bf16 hi, lo; split2(c, hi, lo);
                            bf16* C = (bf16*)Cv;
                            size_t base = (size_t)r * (3 * N) + col;
                            C[base] = hi; C[base + N] = hi; C[base + 2 * N] = lo;
                        } else {
                            float* C = (float*)Cv;
                            if (res) c += res[(size_t)r * N + col];
                            C[(size_t)r * N + col] = c;
                        }
                    }
                }
            }
        }
    }
}

// ---------------- tensor-core flash attention (unchanged, works) ----------------
__global__ void __launch_bounds__(256)
attn_mma_kernel(const bf16* __restrict__ qkv2, bf16* __restrict__ att2)
{
    extern __shared__ char dynsm[];
    bf16* Qs = (bf16*)dynsm;
    bf16* Ks = (bf16*)(dynsm + 51200);
    bf16* Vs = (bf16*)(dynsm + 78848);
    bf16* Ps = (bf16*)(dynsm + 105472);

    const int qb0  = blockIdx.x * 128;
    const int h    = blockIdx.y;
    const int b    = blockIdx.z;
    const int tid  = threadIdx.x;
    const int lane = tid & 31;
    const int w    = tid >> 5;
    const int gid  = lane >> 2, tig = lane & 3;

    const size_t NQ = 3 * E3;
    const size_t rowbase = (size_t)(b * TT) * NQ;
    const int qoff = h * HS, koff = EE + h * HS, voff = 2 * EE + h * HS;
    const int loseg = 2 * E3;

    for (int i = tid; i < 128 * 12; i += 256) {
        int r = i / 12, e0 = (i % 12) * 8;
        const size_t g = rowbase + (size_t)(qb0 + r) * NQ;
        *(uint4*)&Qs[r * 200 + e0]      = *(const uint4*)&qkv2[g + qoff + e0];
        *(uint4*)&Qs[r * 200 + 96 + e0] = *(const uint4*)&qkv2[g + loseg + qoff + e0];
    }

    float o[12][4];
#pragma unroll
    for (int i = 0; i < 12; i++)
#pragma unroll
        for (int j = 0; j < 4; j++) o[i][j] = 0.f;
    float mrow0 = -1e30f, mrow1 = -1e30f, lrow0 = 0.f, lrow1 = 0.f;

    const float scale = 0.10206207261596577f;
    const int nchunks = qb0 / 64 + 2;

    for (int ch = 0; ch < nchunks; ch++) {
        const int c0 = ch * 64;
        __syncthreads();
        for (int i = tid; i < 64 * 12; i += 256) {
            int key = i / 12, e0 = (i % 12) * 8;
            const size_t g = rowbase + (size_t)(c0 + key) * NQ;
            uint4 khiv = *(const uint4*)&qkv2[g + koff + e0];
            uint4 klov = *(const uint4*)&qkv2[g + loseg + koff + e0];
            const bf16* kh = (const bf16*)&khiv;
            const bf16* kl = (const bf16*)&klov;
#pragma unroll
            for (int j = 0; j < 8; j++) {
                Ks[(e0 + j) * 72 + key]      = kh[j];
                Ks[(96 + e0 + j) * 72 + key] = kl[j];
            }
            *(uint4*)&Vs[key * 104 + e0]        = *(const uint4*)&qkv2[g + voff + e0];
            *(uint4*)&Vs[(64 + key) * 104 + e0] = *(const uint4*)&qkv2[g + loseg + voff + e0];
        }
        __syncthreads();

        float sacc[8][4];
#pragma unroll
        for (int i = 0; i < 8; i++)
#pragma unroll
            for (int j = 0; j < 4; j++) sacc[i][j] = 0.f;

#pragma unroll
        for (int sgi = 0; sgi < 3; sgi++) {
            const int qs0 = (sgi == 2) ? 96 : 0;
            const int ks0 = (sgi == 1) ? 96 : 0;
#pragma unroll
            for (int kk = 0; kk < 96; kk += 16) {
                uint32_t a[4];
                ldmA4(a, &Qs[(w * 16 + (lane & 15)) * 200 + qs0 + kk + (lane >> 4) * 8]);
#pragma unroll
                for (int nt = 0; nt < 8; nt += 2) {
                    uint32_t bb[4];
                    ldmB4t(bb, &Ks[(ks0 + kk + (lane & 15)) * 72 + nt * 8 + (lane >> 4) * 8]);
                    mma16816(sacc[nt],     a, bb);
                    mma16816(sacc[nt + 1], a, bb + 2);
                }
            }
        }

        const int rg0 = qb0 + w * 16 + gid;
        const bool need_mask = (c0 + 64 > qb0);
        float cm0 = -1e30f, cm1 = -1e30f;
#pragma unroll
        for (int nt = 0; nt < 8; nt++) {
#pragma unroll
            for (int e = 0; e < 4; e++) {
                float s = sacc[nt][e] * scale;
                if (need_mask) {
                    int col = c0 + nt * 8 + tig * 2 + (e & 1);
                    int row = rg0 + (e >> 1) * 8;
                    if (col > row) s = -1e30f;
                }
                sacc[nt][e] = s;
                if (e < 2) cm0 = fmaxf(cm0, s); else cm1 = fmaxf(cm1, s);
            }
        }
        cm0 = fmaxf(cm0, __shfl_xor_sync(0xffffffffu, cm0, 1));
        cm0 = fmaxf(cm0, __shfl_xor_sync(0xffffffffu, cm0, 2));
        cm1 = fmaxf(cm1, __shfl_xor_sync(0xffffffffu, cm1, 1));
        cm1 = fmaxf(cm1, __shfl_xor_sync(0xffffffffu, cm1, 2));

        const float mn0 = fmaxf(mrow0, cm0), mn1 = fmaxf(mrow1, cm1);
        const float al0 = __expf(mrow0 - mn0), al1 = __expf(mrow1 - mn1);
        float cs0 = 0.f, cs1 = 0.f;
#pragma unroll
        for (int nt = 0; nt < 8; nt++) {
            float p0 = __expf(sacc[nt][0] - mn0), p1 = __expf(sacc[nt][1] - mn0);
            float p2 = __expf(sacc[nt][2] - mn1), p3 = __expf(sacc[nt][3] - mn1);
            cs0 += p0 + p1; cs1 += p2 + p3;
            bf16 h0, l0, h1, l1, h2, l2, h3, l3;
            split2(p0, h0, l0); split2(p1, h1, l1);
            split2(p2, h2, l2); split2(p3, h3, l3);
            int colb = nt * 8 + tig * 2;
            *(uint32_t*)&Ps[(w * 16 + gid) * 136 + colb]          = pack2(h0, h1);
            *(uint32_t*)&Ps[(w * 16 + gid) * 136 + 64 + colb]     = pack2(l0, l1);
            *(uint32_t*)&Ps[(w * 16 + gid + 8) * 136 + colb]      = pack2(h2, h3);
            *(uint32_t*)&Ps[(w * 16 + gid + 8) * 136 + 64 + colb] = pack2(l2, l3);
        }
        cs0 += __shfl_xor_sync(0xffffffffu, cs0, 1);
        cs0 += __shfl_xor_sync(0xffffffffu, cs0, 2);
        cs1 += __shfl_xor_sync(0xffffffffu, cs1, 1);
        cs1 += __shfl_xor_sync(0xffffffffu, cs1, 2);

        lrow0 = lrow0 * al0 + cs0; lrow1 = lrow1 * al1 + cs1;
        mrow0 = mn0; mrow1 = mn1;
#pragma unroll
        for (int nt = 0; nt < 12; nt++) {
            o[nt][0] *= al0; o[nt][1] *= al0; o[nt][2] *= al1; o[nt][3] *= al1;
        }
        __syncwarp();

#pragma unroll
        for (int sgi = 0; sgi < 3; sgi++) {
            const int as0 = (sgi == 2) ? 64 : 0;
            const int bs0 = (sgi == 1) ? 64 : 0;
#pragma unroll
            for (int kk = 0; kk < 64; kk += 16) {
                uint32_t a[4];
                ldmA4(a, &Ps[(w * 16 + (lane & 15)) * 136 + as0 + kk + (lane >> 4) * 8]);
#pragma unroll
                for (int nt = 0; nt < 12; nt += 2) {
                    uint32_t bb[4];
                    ldmB4t(bb, &Vs[(bs0 + kk + (lane & 15)) * 104 + nt * 8 + (lane >> 4) * 8]);
                    mma16816(o[nt],     a, bb);
                    mma16816(o[nt + 1], a, bb + 2);
                }
            }
        }
    }

    const float iv0 = 1.f / lrow0, iv1 = 1.f / lrow1;
#pragma unroll
    for (int nt = 0; nt < 12; nt++) {
        int d = h * HS + nt * 8 + tig * 2;
        {
            size_t orow = (size_t)(b * TT + qb0 + w * 16 + gid) * E3;
            float v0 = o[nt][0] * iv0, v1 = o[nt][1] * iv0;
            bf16 h0, l0, h1, l1; split2(v0, h0, l0); split2(v1, h1, l1);
            *(uint32_t*)&att2[orow + d]          = pack2(h0, h1);
            *(uint32_t*)&att2[orow + EE + d]     = pack2(h0, h1);
            *(uint32_t*)&att2[orow + 2 * EE + d] = pack2(l0, l1);
        }
        {
            size_t orow = (size_t)(b * TT + qb0 + w * 16 + gid + 8) * E3;
            float v0 = o[nt][2] * iv1, v1 = o[nt][3] * iv1;
            bf16 h0, l0, h1, l1; split2(v0, h0, l0); split2(v1, h1, l1);
            *(uint32_t*)&att2[orow + d]          = pack2(h0, h1);
            *(uint32_t*)&att2[orow + EE + d]     = pack2(h0, h1);
            *(uint32_t*)&att2[orow + 2 * EE + d] = pack2(l0, l1);
        }
    }
}

// ---------------- loss ----------------
__global__ void loss_zero_kernel(float* loss) { *loss = 0.f; }

__global__ void loss_kernel(const float* __restrict__ logits,
                            const int* __restrict__ targets,
                            float* __restrict__ loss)
{
    const int row = blockIdx.x;
    const int tid = threadIdx.x;   // 256
    const float* lr = logits + (size_t)row * VV;

    float m = -1e30f, s = 0.f;
    for (int j = tid; j < VV; j += 256) {
        float v = lr[j];
        if (v > m) { s = s * __expf(m - v) + 1.f; m = v; }
        else       { s += __expf(v - m); }
    }
    __shared__ float rm[256], rs[256];
    rm[tid] = m; rs[tid] = s; __syncthreads();
    for (int o = 128; o > 0; o >>= 1) {
        if (tid < o) {
            float m2 = rm[tid + o], s2 = rs[tid + o];
            float mm = fmaxf(rm[tid], m2);
            rs[tid] = rs[tid] * __expf(rm[tid] - mm) + s2 * __expf(m2 - mm);
            rm[tid] = mm;
        }
        __syncthreads();
    }
    if (tid == 0) {
        float lp = lr[targets[row]] - rm[0] - logf(rs[0]);
        atomicAdd(loss, -lp * (1.f / (float)MM));
    }
}

// ---------------- launch ----------------
extern "C" void kernel_launch(void* const* d_in, const int* in_sizes, int n_in,
                              void* d_out, int out_size)
{
    const int*   idx     = (const int*)  d_in[0];
    const int*   targets = (const int*)  d_in[1];
    const float* tok     = (const float*)d_in[2];
    const float* pos     = (const float*)d_in[3];
    const float* Wq      = (const float*)d_in[4];
    const float* Wk      = (const float*)d_in[5];
    const float* Wv      = (const float*)d_in[6];
    const float* Wo      = (const float*)d_in[7];
    const float* bo      = (const float*)d_in[8];
    const float* ln1_g   = (const float*)d_in[9];
    const float* ln1_b   = (const float*)d_in[10];
    const float* ln2_g   = (const float*)d_in[11];
    const float* ln2_b   = (const float*)d_in[12];
    const float* W1      = (const float*)d_in[13];
    const float* b1      = (const float*)d_in[14];
    const float* W2      = (const float*)d_in[15];
    const float* b2      = (const float*)d_in[16];
    const float* lnf_g   = (const float*)d_in[17];
    const float* lnf_b   = (const float*)d_in[18];

    float *x, *lg_scratch;
    bf16 *xn2, *qkv2, *att2, *h42, *wqkv2, *wo2, *w12, *w22, *tok2;
    cudaGetSymbolAddress((void**)&x,    g_x);
    cudaGetSymbolAddress((void**)&xn2,  g_xn2);
    cudaGetSymbolAddress((void**)&qkv2, g_qkv2);
    cudaGetSymbolAddress((void**)&att2, g_att2);
    cudaGetSymbolAddress((void**)&h42,  g_h42);
    cudaGetSymbolAddress((void**)&wqkv2,g_wqkv2);
    cudaGetSymbolAddress((void**)&wo2,  g_wo2);
    cudaGetSymbolAddress((void**)&w12,  g_w12);
    cudaGetSymbolAddress((void**)&w22,  g_w22);
    cudaGetSymbolAddress((void**)&tok2, g_tok2);
    cudaGetSymbolAddress((void**)&lg_scratch, g_logits_scratch);

    const int SMEM128 = 73728;
    const int SMEM256 = 106496;
    const int ATTN_SMEM = 140288;
    cudaFuncSetAttribute(mma_gemm<8,false,true >, cudaFuncAttributeMaxDynamicSharedMemorySize, SMEM256);
    cudaFuncSetAttribute(mma_gemm<8,true ,true >, cudaFuncAttributeMaxDynamicSharedMemorySize, SMEM256);
    cudaFuncSetAttribute(mma_gemm<8,false,false>, cudaFuncAttributeMaxDynamicSharedMemorySize, SMEM256);
    cudaFuncSetAttribute(mma_gemm<4,false,false>, cudaFuncAttributeMaxDynamicSharedMemorySize, SMEM128);
    cudaFuncSetAttribute(attn_mma_kernel, cudaFuncAttributeMaxDynamicSharedMemorySize, ATTN_SMEM);

    const bool out_holds_logits = ((long long)out_size >= (long long)MM * VV);
    float* logits = out_holds_logits ? (float*)d_out : lg_scratch;
    float* loss_ptr = out_holds_logits ? ((float*)d_out + (size_t)MM * VV)
                                       : (float*)d_out;
    const bool do_loss = (!out_holds_logits || (long long)out_size > (long long)MM * VV);

    // launch order chosen so ncu (-s 5 -c 1) captures the 6th launch = QKV GEMM:
    // 1 convert_all, 2 convert_tok, 3 embed, 4 loss_zero, 5 ln, 6 qkv_gemm
    convert_all_kernel<<<dim3(9216, 48), 256>>>(Wq, Wk, Wv, Wo, W1, W2);
    convert_tok_kernel<<<dim3(EE / 32, VV / 32), dim3(32, 32)>>>(tok, tok2);
    {
        size_t n = (size_t)MM * EE;
        embed_kernel<<<(unsigned)((n + 255) / 256), 256>>>(idx, tok, pos, x);
    }
    if (do_loss) loss_zero_kernel<<<1, 1>>>(loss_ptr);

    auto pgrid = [&](int N, int TN, int maxcta) {
        int t = (MM / 128) * (N / TN); return t < maxcta ? t : maxcta;
    };
    const int gQKV = pgrid(E3, 256, 148);
    const int gEc  = pgrid(EE, 128, 296);
    const int gFc  = pgrid(FF, 256, 148);
    const int gVc  = pgrid(VV, 256, 148);

    for (int l = 0; l < LL; l++) {
        ln_split_kernel<<<MM, 256>>>(x, ln1_g + (size_t)l * EE, ln1_b + (size_t)l * EE, xn2);
        mma_gemm<8, false, true><<<gQKV, 256, SMEM256>>>(xn2, wqkv2 + (size_t)l * E3 * E3,
                                                         nullptr, nullptr, qkv2, MM, E3, E3);
        attn_mma_kernel<<<dim3(TT / 128, HH, BB), 256, ATTN_SMEM>>>(qkv2, att2);
        mma_gemm<4, false, false><<<gEc, 256, SMEM128>>>(att2, wo2 + (size_t)l * E3 * EE,
                                                         bo + (size_t)l * EE, x, x, MM, EE, E3);
        ln_split_kernel<<<MM, 256>>>(x, ln2_g + (size_t)l * EE, ln2_b + (size_t)l * EE, xn2);
        mma_gemm<8, true, true><<<gFc, 256, SMEM256>>>(xn2, w12 + (size_t)l * E3 * FF,
                                                       b1 + (size_t)l * FF, nullptr, h42, MM, FF, E3);
        mma_gemm<4, false, false><<<gEc, 256, SMEM128>>>(h42, w22 + (size_t)l * F3 * EE,
                                                         b2 + (size_t)l * EE, x, x, MM, EE, F3);
    }

    ln_split_kernel<<<MM, 256>>>(x, lnf_g, lnf_b, xn2);
    mma_gemm<8, false, false><<<gVc, 256, SMEM256>>>(xn2, tok2, nullptr, nullptr, logits, MM, VV, E3);

    if (do_loss) loss_kernel<<<MM, 256>>>(logits, targets, loss_ptr);
}

// round 10
// speedup vs baseline: 1.4526x; 1.4526x over previous
#include <cuda_runtime.h>
#include <cuda_fp16.h>
#include <math.h>
#include <stdint.h>

// ---------------- problem constants ----------------
#define BB 4
#define TT 1024
#define EE 768
#define HH 8
#define HS 96
#define LL 8
#define VV 32000
#define FF 3072            // 4*E
#define MM (BB*TT)         // 4096 rows
#define E2 (2*EE)          // 1536 (2-term split K for E)
#define E3 (3*EE)          // 2304 (QKV output width q|k|v)
#define F2 (2*FF)          // 6144

typedef __half fp16;

// ---------------- scratch (device globals; no allocation allowed) ----------------
__device__ __align__(256) float g_x   [(size_t)MM*EE];
__device__ __align__(256) fp16  g_xn2 [(size_t)MM*E2];
__device__ __align__(256) fp16  g_qkv2[(size_t)MM*2*E3];       // [M][hi(2304) | lo(2304)]
__device__ __align__(256) fp16  g_att2[(size_t)MM*E2];
__device__ __align__(256) fp16  g_h42 [(size_t)MM*F2];

// weights, B-layout [2K rows][N cols], both K-blocks = round(W) fp16
__device__ __align__(256) fp16  g_wqkv2[(size_t)LL*E2*E3];
__device__ __align__(256) fp16  g_wo2  [(size_t)LL*E2*EE];
__device__ __align__(256) fp16  g_w12  [(size_t)LL*E2*FF];
__device__ __align__(256) fp16  g_w22  [(size_t)LL*F2*EE];
__device__ __align__(256) fp16  g_tok2 [(size_t)E2*VV];

__device__ __align__(256) float g_logits_scratch[(size_t)MM*VV];

// ---------------- helpers ----------------
__device__ __forceinline__ void split2h(float v, fp16& hi, fp16& lo) {
    hi = __float2half(v);
    lo = __float2half(v - __half2float(hi));
}
__device__ __forceinline__ uint32_t pack2h(fp16 a, fp16 b) {
    uint16_t x = *(uint16_t*)&a, y = *(uint16_t*)&b;
    return (uint32_t)x | ((uint32_t)y << 16);
}
__device__ __forceinline__ void cp16(void* dst_smem, const void* src_gmem) {
    uint32_t s = (uint32_t)__cvta_generic_to_shared(dst_smem);
    asm volatile("cp.async.cg.shared.global [%0], [%1], 16;\n" :: "r"(s), "l"(src_gmem));
}
__device__ __forceinline__ void cp_commit() { asm volatile("cp.async.commit_group;\n" ::: "memory"); }
__device__ __forceinline__ void cp_wait1()  { asm volatile("cp.async.wait_group 1;\n" ::: "memory"); }

__device__ __forceinline__ void ldmA4(uint32_t* a, const void* p) {
    uint32_t s = (uint32_t)__cvta_generic_to_shared(p);
    asm volatile("ldmatrix.sync.aligned.m8n8.x4.shared.b16 {%0,%1,%2,%3}, [%4];"
                 : "=r"(a[0]), "=r"(a[1]), "=r"(a[2]), "=r"(a[3]) : "r"(s));
}
__device__ __forceinline__ void ldmB4t(uint32_t* b, const void* p) {
    uint32_t s = (uint32_t)__cvta_generic_to_shared(p);
    asm volatile("ldmatrix.sync.aligned.m8n8.x4.trans.shared.b16 {%0,%1,%2,%3}, [%4];"
                 : "=r"(b[0]), "=r"(b[1]), "=r"(b[2]), "=r"(b[3]) : "r"(s));
}
__device__ __forceinline__ void mma16816h(float* c, const uint32_t* a, const uint32_t* b) {
    asm volatile(
        "mma.sync.aligned.m16n8k16.row.col.f32.f16.f16.f32 "
        "{%0,%1,%2,%3},{%4,%5,%6,%7},{%8,%9},{%0,%1,%2,%3};"
        : "+f"(c[0]), "+f"(c[1]), "+f"(c[2]), "+f"(c[3])
        : "r"(a[0]), "r"(a[1]), "r"(a[2]), "r"(a[3]), "r"(b[0]), "r"(b[1]));
}

// ---------------- batched weight conversion (all layers, all 6 tensors) -------------
// W[K,N] fp32 -> B [2K][N], both row blocks = round(W).
__global__ void convert_all_kernel(const float* __restrict__ Wq, const float* __restrict__ Wk,
                                   const float* __restrict__ Wv, const float* __restrict__ Wo,
                                   const float* __restrict__ W1, const float* __restrict__ W2)
{
    const int l = blockIdx.y / 6, seg = blockIdx.y % 6;
    const float* W; fp16* out; int K, N, pitch, colOff;
    switch (seg) {
        case 0: W = Wq + (size_t)l*EE*EE; out = g_wqkv2 + (size_t)l*E2*E3; K=EE; N=EE; pitch=E3; colOff=0;    break;
        case 1: W = Wk + (size_t)l*EE*EE; out = g_wqkv2 + (size_t)l*E2*E3; K=EE; N=EE; pitch=E3; colOff=EE;   break;
        case 2: W = Wv + (size_t)l*EE*EE; out = g_wqkv2 + (size_t)l*E2*E3; K=EE; N=EE; pitch=E3; colOff=2*EE; break;
        case 3: W = Wo + (size_t)l*EE*EE; out = g_wo2   + (size_t)l*E2*EE; K=EE; N=EE; pitch=EE; colOff=0;    break;
        case 4: W = W1 + (size_t)l*EE*FF; out = g_w12   + (size_t)l*E2*FF; K=EE; N=FF; pitch=FF; colOff=0;    break;
        default:W = W2 + (size_t)l*FF*EE; out = g_w22   + (size_t)l*F2*EE; K=FF; N=EE; pitch=EE; colOff=0;    break;
    }
    int i = blockIdx.x * 256 + threadIdx.x;
    if (i >= K * N) return;
    int k = i / N, n = i % N;
    fp16 hi = __float2half(W[i]);
    out[(size_t)k * pitch + colOff + n]       = hi;
    out[(size_t)(K + k) * pitch + colOff + n] = hi;
}

// Contract: A segments [hi | lo] (fp16), B row-blocks [hi; hi]
//   C = (Ahi + Alo) * round(B) = A * round(B); error = B-rounding only (~2^-11)

// ---------------- tok transpose: out[2E, V] from tok[V, E] (B-side) ----------------
__global__ void convert_tok_kernel(const float* __restrict__ tok, fp16* __restrict__ out)
{
    __shared__ float t[32][33];
    int k0 = blockIdx.x * 32, n0 = blockIdx.y * 32;
    int tx = threadIdx.x, ty = threadIdx.y;
    t[ty][tx] = tok[(size_t)(n0 + ty) * EE + k0 + tx];
    __syncthreads();
    fp16 hi = __float2half(t[tx][ty]);
    size_t k = k0 + ty, n = n0 + tx;
    out[k * VV + n]        = hi;
    out[(EE + k) * VV + n] = hi;
}

// ---------------- embedding ----------------
__global__ void embed_kernel(const int* __restrict__ idx,
                             const float* __restrict__ tok,
                             const float* __restrict__ pos,
                             float* __restrict__ x)
{
    size_t i = (size_t)blockIdx.x * blockDim.x + threadIdx.x;
    if (i >= (size_t)MM * EE) return;
    int e  = (int)(i % EE);
    int bt = (int)(i / EE);
    int t  = bt % TT;
    x[i] = tok[(size_t)idx[bt] * EE + e] + pos[(size_t)t * EE + e];
}

// ---------------- layernorm -> A-side fp16 [row, 2E]: [hi | lo] ----------------
__global__ void ln_split_kernel(const float* __restrict__ x,
                                const float* __restrict__ g,
                                const float* __restrict__ b,
                                fp16* __restrict__ out)
{
    int row = blockIdx.x;
    int tid = threadIdx.x;  // 256
    const float* xr = x + (size_t)row * EE;
    float s = 0.f, s2 = 0.f;
    for (int e = tid; e < EE; e += 256) { float v = xr[e]; s += v; s2 += v * v; }
    __shared__ float r1[256], r2[256];
    r1[tid] = s; r2[tid] = s2; __syncthreads();
    for (int o = 128; o > 0; o >>= 1) {
        if (tid < o) { r1[tid] += r1[tid + o]; r2[tid] += r2[tid + o]; }
        __syncthreads();
    }
    float mean = r1[0] * (1.f / EE);
    float var  = r2[0] * (1.f / EE) - mean * mean;
    float inv  = rsqrtf(var + 1e-5f);
    fp16* orow = out + (size_t)row * E2;
    for (int e = tid; e < EE; e += 256) {
        float v = (xr[e] - mean) * inv * g[e] + b[e];
        fp16 hi, lo; split2h(v, hi, lo);
        orow[e] = hi; orow[EE + e] = lo;
    }
}

// ---------------- tensor-core GEMM: C[M,N] = A[M,K2] @ B[K2,N] (fp16, fp32 acc) --------
// R6-best config: block 128x128, warp 64x32, K-tile 64, 2-stage cp.async, 2 CTAs/SM,
// persistent CTAs in col-major tile order. Dynamic smem = 73728 B.
template<bool GELU, bool SPLIT>
__global__ void __launch_bounds__(256, 2)
mma_gemm(const fp16* __restrict__ A, const fp16* __restrict__ B,
         const float* __restrict__ bias, const float* __restrict__ res,
         void* __restrict__ Cv, int M, int N, int K2)
{
    extern __shared__ char dynsm[];
    fp16* As = (fp16*)dynsm;             // [2][128*72]
    fp16* Bs = (fp16*)dynsm + 18432;     // [2][64*144]

    const int tid  = threadIdx.x;
    const int lane = tid & 31;
    const int warp = tid >> 5;
    const int wm   = warp & 1;
    const int wn   = warp >> 1;

    const int nRowT = M >> 7;
    const int nColT = N >> 7;
    const int nTiles = nRowT * nColT;
    const int ntk = K2 >> 6;

    for (int tile = blockIdx.x; tile < nTiles; tile += gridDim.x) {
        const int col0 = (tile / nRowT) * 128;
        const int row0 = (tile % nRowT) * 128;

        float acc[4][4][4];
#pragma unroll
        for (int i = 0; i < 4; i++)
#pragma unroll
            for (int j = 0; j < 4; j++)
#pragma unroll
                for (int r = 0; r < 4; r++) acc[i][j][r] = 0.f;

        auto load_tile = [&](int s, int k0) {
#pragma unroll
            for (int i = 0; i < 4; i++) {
                int idx = tid + i * 256;
                int r = idx >> 3, c = (idx & 7) * 8;
                cp16(&As[s * 9216 + r * 72 + c], &A[(size_t)(row0 + r) * K2 + k0 + c]);
            }
#pragma unroll
            for (int i = 0; i < 4; i++) {
                int idx = tid + i * 256;
                int r = idx >> 4, c = (idx & 15) * 8;
                cp16(&Bs[s * 9216 + r * 144 + c], &B[(size_t)(k0 + r) * N + col0 + c]);
            }
        };

        __syncthreads();
        load_tile(0, 0);
        cp_commit();

        for (int t = 0; t < ntk; t++) {
            if (t + 1 < ntk) load_tile((t + 1) & 1, (t + 1) * 64);
            cp_commit();
            cp_wait1();
            __syncthreads();
            const int s = t & 1;

#pragma unroll
            for (int kk = 0; kk < 64; kk += 16) {
                uint32_t a[4][4], b[2][4];
#pragma unroll
                for (int mi = 0; mi < 4; mi++)
                    ldmA4(a[mi], &As[s * 9216 + (wm * 64 + mi * 16 + (lane & 15)) * 72 + kk + (lane >> 4) * 8]);
#pragma unroll
                for (int nj = 0; nj < 2; nj++)
                    ldmB4t(b[nj], &Bs[s * 9216 + (kk + (lane & 15)) * 144 + wn * 32 + nj * 16 + (lane >> 4) * 8]);
#pragma unroll
                for (int mi = 0; mi < 4; mi++) {
                    mma16816h(acc[mi][0], a[mi], b[0]);
                    mma16816h(acc[mi][1], a[mi], b[0] + 2);
                    mma16816h(acc[mi][2], a[mi], b[1]);
                    mma16816h(acc[mi][3], a[mi], b[1] + 2);
                }
            }
            __syncthreads();
        }

        // ---- epilogue ----
        const int gid = lane >> 2, tig = lane & 3;
#pragma unroll
        for (int mi = 0; mi < 4; mi++) {
#pragma unroll
            for (int ni = 0; ni < 4; ni++) {
                int gr = row0 + wm * 64 + mi * 16 + gid;
                int gc = col0 + wn * 32 + ni * 8 + tig * 2;
#pragma unroll
                for (int half = 0; half < 2; half++) {
                    int r = gr + half * 8;
#pragma unroll
                    for (int cc = 0; cc < 2; cc++) {
                        float c = acc[mi][ni][half * 2 + cc];
                        int col = gc + cc;
                        if (bias) c += bias[col];
                        if (GELU) c = 0.5f * c * (1.f + erff(c * 0.70710678118654752f));
                        if (SPLIT) {
                            fp16 hi, lo; split2h(c, hi, lo);
                            fp16* C = (fp16*)Cv;
                            size_t base = (size_t)r * (2 * N) + col;
                            C[base] = hi; C[base + N] = lo;
                        } else {
                            float* C = (float*)Cv;
                            if (res) c += res[(size_t)r * N + col];
                            C[(size_t)r * N + col] = c;
                        }
                    }
                }
            }
        }
    }
}

// ---------------- fp16 flash attention ----------------
// qkv2: [M][2*E3] fp16 ([hi(q|k|v) | lo(q|k|v)]). att2: [M][2*EE] = [hi | lo].
// Block: 128 queries x (head, batch). 256 thr = 8 warps x 16 rows.
// Smem: Qs[128][200] (hi|lo) @0 (51200), Ks[96][72] hi @51200 (13824),
//       Vs[64][104] hi @65024 (13312), Ps[128][72] hi @78336 (18432). Total 96768.
__global__ void __launch_bounds__(256)
attn_mma_kernel(const fp16* __restrict__ qkv2, fp16* __restrict__ att2)
{
    extern __shared__ char dynsm[];
    fp16* Qs = (fp16*)dynsm;
    fp16* Ks = (fp16*)(dynsm + 51200);
    fp16* Vs = (fp16*)(dynsm + 65024);
    fp16* Ps = (fp16*)(dynsm + 78336);

    const int qb0  = blockIdx.x * 128;
    const int h    = blockIdx.y;
    const int b    = blockIdx.z;
    const int tid  = threadIdx.x;
    const int lane = tid & 31;
    const int w    = tid >> 5;
    const int gid  = lane >> 2, tig = lane & 3;

    const size_t NQ = 2 * E3;
    const size_t rowbase = (size_t)(b * TT) * NQ;
    const int qoff = h * HS, koff = EE + h * HS, voff = 2 * EE + h * HS;

    // Q tile: hi + lo segments
    for (int i = tid; i < 128 * 12; i += 256) {
        int r = i / 12, e0 = (i % 12) * 8;
        const size_t g = rowbase + (size_t)(qb0 + r) * NQ;
        *(uint4*)&Qs[r * 200 + e0]      = *(const uint4*)&qkv2[g + qoff + e0];
        *(uint4*)&Qs[r * 200 + 96 + e0] = *(const uint4*)&qkv2[g + E3 + qoff + e0];
    }

    float o[12][4];
#pragma unroll
    for (int i = 0; i < 12; i++)
#pragma unroll
        for (int j = 0; j < 4; j++) o[i][j] = 0.f;
    float mrow0 = -1e30f, mrow1 = -1e30f, lrow0 = 0.f, lrow1 = 0.f;

    const float scale = 0.10206207261596577f;
    const int nchunks = qb0 / 64 + 2;

    for (int ch = 0; ch < nchunks; ch++) {
        const int c0 = ch * 64;
        __syncthreads();
        // K (hi, transposed) and V (hi) chunk
        for (int i = tid; i < 64 * 12; i += 256) {
            int key = i / 12, e0 = (i % 12) * 8;
            const size_t g = rowbase + (size_t)(c0 + key) * NQ;
            uint4 khiv = *(const uint4*)&qkv2[g + koff + e0];
            const fp16* kh = (const fp16*)&khiv;
#pragma unroll
            for (int j = 0; j < 8; j++)
                Ks[(e0 + j) * 72 + key] = kh[j];
            *(uint4*)&Vs[key * 104 + e0] = *(const uint4*)&qkv2[g + voff + e0];
        }
        __syncthreads();

        // ---- S = Q Khi^T (2 segments: Qhi, Qlo) ----
        float sacc[8][4];
#pragma unroll
        for (int i = 0; i < 8; i++)
#pragma unroll
            for (int j = 0; j < 4; j++) sacc[i][j] = 0.f;

#pragma unroll
        for (int sgi = 0; sgi < 2; sgi++) {
            const int qs0 = sgi * 96;
#pragma unroll
            for (int kk = 0; kk < 96; kk += 16) {
                uint32_t a[4];
                ldmA4(a, &Qs[(w * 16 + (lane & 15)) * 200 + qs0 + kk + (lane >> 4) * 8]);
#pragma unroll
                for (int nt = 0; nt < 8; nt += 2) {
                    uint32_t bb[4];
                    ldmB4t(bb, &Ks[(kk + (lane & 15)) * 72 + nt * 8 + (lane >> 4) * 8]);
                    mma16816h(sacc[nt],     a, bb);
                    mma16816h(sacc[nt + 1], a, bb + 2);
                }
            }
        }

        // ---- scale + causal mask + online softmax ----
        const int rg0 = qb0 + w * 16 + gid;
        const bool need_mask = (c0 + 64 > qb0);
        float cm0 = -1e30f, cm1 = -1e30f;
#pragma unroll
        for (int nt = 0; nt < 8; nt++) {
#pragma unroll
            for (int e = 0; e < 4; e++) {
                float s = sacc[nt][e] * scale;
                if (need_mask) {
                    int col = c0 + nt * 8 + tig * 2 + (e & 1);
                    int row = rg0 + (e >> 1) * 8;
                    if (col > row) s = -1e30f;
                }
                sacc[nt][e] = s;
                if (e < 2) cm0 = fmaxf(cm0, s); else cm1 = fmaxf(cm1, s);
            }
        }
        cm0 = fmaxf(cm0, __shfl_xor_sync(0xffffffffu, cm0, 1));
        cm0 = fmaxf(cm0, __shfl_xor_sync(0xffffffffu, cm0, 2));
        cm1 = fmaxf(cm1, __shfl_xor_sync(0xffffffffu, cm1, 1));
        cm1 = fmaxf(cm1, __shfl_xor_sync(0xffffffffu, cm1, 2));

        const float mn0 = fmaxf(mrow0, cm0), mn1 = fmaxf(mrow1, cm1);
        const float al0 = __expf(mrow0 - mn0), al1 = __expf(mrow1 - mn1);
        float cs0 = 0.f, cs1 = 0.f;
#pragma unroll
        for (int nt = 0; nt < 8; nt++) {
            float p0 = __expf(sacc[nt][0] - mn0), p1 = __expf(sacc[nt][1] - mn0);
            float p2 = __expf(sacc[nt][2] - mn1), p3 = __expf(sacc[nt][3] - mn1);
            cs0 += p0 + p1; cs1 += p2 + p3;
            int colb = nt * 8 + tig * 2;
            *(uint32_t*)&Ps[(w * 16 + gid) * 72 + colb]     = pack2h(__float2half(p0), __float2half(p1));
            *(uint32_t*)&Ps[(w * 16 + gid + 8) * 72 + colb] = pack2h(__float2half(p2), __float2half(p3));
        }
        cs0 += __shfl_xor_sync(0xffffffffu, cs0, 1);
        cs0 += __shfl_xor_sync(0xffffffffu, cs0, 2);
        cs1 += __shfl_xor_sync(0xffffffffu, cs1, 1);
        cs1 += __shfl_xor_sync(0xffffffffu, cs1, 2);

        lrow0 = lrow0 * al0 + cs0; lrow1 = lrow1 * al1 + cs1;
        mrow0 = mn0; mrow1 = mn1;
#pragma unroll
        for (int nt = 0; nt < 12; nt++) {
            o[nt][0] *= al0; o[nt][1] *= al0; o[nt][2] *= al1; o[nt][3] *= al1;
        }
        __syncwarp();

        // ---- O += P V (single fp16 pass) ----
#pragma unroll
        for (int kk = 0; kk < 64; kk += 16) {
            uint32_t a[4];
            ldmA4(a, &Ps[(w * 16 + (lane & 15)) * 72 + kk + (lane >> 4) * 8]);
#pragma unroll
            for (int nt = 0; nt < 12; nt += 2) {
                uint32_t bb[4];
                ldmB4t(bb, &Vs[(kk + (lane & 15)) * 104 + nt * 8 + (lane >> 4) * 8]);
                mma16816h(o[nt],     a, bb);
                mma16816h(o[nt + 1], a, bb + 2);
            }
        }
    }

    // ---- epilogue: O /= l, write att2 [hi | lo] ----
    const float iv0 = 1.f / lrow0, iv1 = 1.f / lrow1;
#pragma unroll
    for (int nt = 0; nt < 12; nt++) {
        int d = h * HS + nt * 8 + tig * 2;
        {
            size_t orow = (size_t)(b * TT + qb0 + w * 16 + gid) * E2;
            float v0 = o[nt][0] * iv0, v1 = o[nt][1] * iv0;
            fp16 h0, l0, h1, l1; split2h(v0, h0, l0); split2h(v1, h1, l1);
            *(uint32_t*)&att2[orow + d]      = pack2h(h0, h1);
            *(uint32_t*)&att2[orow + EE + d] = pack2h(l0, l1);
        }
        {
            size_t orow = (size_t)(b * TT + qb0 + w * 16 + gid + 8) * E2;
            float v0 = o[nt][2] * iv1, v1 = o[nt][3] * iv1;
            fp16 h0, l0, h1, l1; split2h(v0, h0, l0); split2h(v1, h1, l1);
            *(uint32_t*)&att2[orow + d]      = pack2h(h0, h1);
            *(uint32_t*)&att2[orow + EE + d] = pack2h(l0, l1);
        }
    }
}

// ---------------- loss (single pass, online logsumexp) ----------------
__global__ void loss_zero_kernel(float* loss) { *loss = 0.f; }

__global__ void loss_kernel(const float* __restrict__ logits,
                            const int* __restrict__ targets,
                            float* __restrict__ loss)
{
    const int row = blockIdx.x;
    const int tid = threadIdx.x;   // 256
    const float* lr = logits + (size_t)row * VV;

    float m = -1e30f, s = 0.f;
    for (int j = tid; j < VV; j += 256) {
        float v = lr[j];
        if (v > m) { s = s * __expf(m - v) + 1.f; m = v; }
        else       { s += __expf(v - m); }
    }
    __shared__ float rm[256], rs[256];
    rm[tid] = m; rs[tid] = s; __syncthreads();
    for (int o = 128; o > 0; o >>= 1) {
        if (tid < o) {
            float m2 = rm[tid + o], s2 = rs[tid + o];
            float mm = fmaxf(rm[tid], m2);
            rs[tid] = rs[tid] * __expf(rm[tid] - mm) + s2 * __expf(m2 - mm);
            rm[tid] = mm;
        }
        __syncthreads();
    }
    if (tid == 0) {
        float lp = lr[targets[row]] - rm[0] - logf(rs[0]);
        atomicAdd(loss, -lp * (1.f / (float)MM));
    }
}

// ---------------- launch ----------------
extern "C" void kernel_launch(void* const* d_in, const int* in_sizes, int n_in,
                              void* d_out, int out_size)
{
    const int*   idx     = (const int*)  d_in[0];
    const int*   targets = (const int*)  d_in[1];
    const float* tok     = (const float*)d_in[2];
    const float* pos     = (const float*)d_in[3];
    const float* Wq      = (const float*)d_in[4];
    const float* Wk      = (const float*)d_in[5];
    const float* Wv      = (const float*)d_in[6];
    const float* Wo      = (const float*)d_in[7];
    const float* bo      = (const float*)d_in[8];
    const float* ln1_g   = (const float*)d_in[9];
    const float* ln1_b   = (const float*)d_in[10];
    const float* ln2_g   = (const float*)d_in[11];
    const float* ln2_b   = (const float*)d_in[12];
    const float* W1      = (const float*)d_in[13];
    const float* b1      = (const float*)d_in[14];
    const float* W2      = (const float*)d_in[15];
    const float* b2      = (const float*)d_in[16];
    const float* lnf_g   = (const float*)d_in[17];
    const float* lnf_b   = (const float*)d_in[18];

    float *x, *lg_scratch;
    fp16 *xn2, *qkv2, *att2, *h42, *wqkv2, *wo2, *w12, *w22, *tok2;
    cudaGetSymbolAddress((void**)&x,    g_x);
    cudaGetSymbolAddress((void**)&xn2,  g_xn2);
    cudaGetSymbolAddress((void**)&qkv2, g_qkv2);
    cudaGetSymbolAddress((void**)&att2, g_att2);
    cudaGetSymbolAddress((void**)&h42,  g_h42);
    cudaGetSymbolAddress((void**)&wqkv2,g_wqkv2);
    cudaGetSymbolAddress((void**)&wo2,  g_wo2);
    cudaGetSymbolAddress((void**)&w12,  g_w12);
    cudaGetSymbolAddress((void**)&w22,  g_w22);
    cudaGetSymbolAddress((void**)&tok2, g_tok2);
    cudaGetSymbolAddress((void**)&lg_scratch, g_logits_scratch);

    const int GEMM_SMEM = 73728;
    const int ATTN_SMEM = 96768;
    cudaFuncSetAttribute(mma_gemm<false,true >, cudaFuncAttributeMaxDynamicSharedMemorySize, GEMM_SMEM);
    cudaFuncSetAttribute(mma_gemm<true ,true >, cudaFuncAttributeMaxDynamicSharedMemorySize, GEMM_SMEM);
    cudaFuncSetAttribute(mma_gemm<false,false>, cudaFuncAttributeMaxDynamicSharedMemorySize, GEMM_SMEM);
    cudaFuncSetAttribute(attn_mma_kernel, cudaFuncAttributeMaxDynamicSharedMemorySize, ATTN_SMEM);

    const bool out_holds_logits = ((long long)out_size >= (long long)MM * VV);
    float* logits = out_holds_logits ? (float*)d_out : lg_scratch;
    float* loss_ptr = out_holds_logits ? ((float*)d_out + (size_t)MM * VV)
                                       : (float*)d_out;
    const bool do_loss = (!out_holds_logits || (long long)out_size > (long long)MM * VV);

    convert_all_kernel<<<dim3(9216, 48), 256>>>(Wq, Wk, Wv, Wo, W1, W2);
    convert_tok_kernel<<<dim3(EE / 32, VV / 32), dim3(32, 32)>>>(tok, tok2);
    {
        size_t n = (size_t)MM * EE;
        embed_kernel<<<(unsigned)((n + 255) / 256), 256>>>(idx, tok, pos, x);
    }
    if (do_loss) loss_zero_kernel<<<1, 1>>>(loss_ptr);

    const int MAXCTA = 296;   // 2 CTAs/SM
    auto pgrid = [&](int N) { int t = (MM / 128) * (N / 128); return t < MAXCTA ? t : MAXCTA; };
    const int gQKV = pgrid(E3);
    const int gEc  = pgrid(EE);
    const int gFc  = pgrid(FF);
    const int gVc  = pgrid(VV);

    for (int l = 0; l < LL; l++) {
        ln_split_kernel<<<MM, 256>>>(x, ln1_g + (size_t)l * EE, ln1_b + (size_t)l * EE, xn2);
        mma_gemm<false, true><<<gQKV, 256, GEMM_SMEM>>>(xn2, wqkv2 + (size_t)l * E2 * E3,
                                                        nullptr, nullptr, qkv2, MM, E3, E2);
        attn_mma_kernel<<<dim3(TT / 128, HH, BB), 256, ATTN_SMEM>>>(qkv2, att2);
        mma_gemm<false, false><<<gEc, 256, GEMM_SMEM>>>(att2, wo2 + (size_t)l * E2 * EE,
                                                        bo + (size_t)l * EE, x, x, MM, EE, E2);
        ln_split_kernel<<<MM, 256>>>(x, ln2_g + (size_t)l * EE, ln2_b + (size_t)l * EE, xn2);
        mma_gemm<true, true><<<gFc, 256, GEMM_SMEM>>>(xn2, w12 + (size_t)l * E2 * FF,
                                                      b1 + (size_t)l * FF, nullptr, h42, MM, FF, E2);
        mma_gemm<false, false><<<gEc, 256, GEMM_SMEM>>>(h42, w22 + (size_t)l * F2 * EE,
                                                        b2 + (size_t)l * EE, x, x, MM, EE, F2);
    }

    ln_split_kernel<<<MM, 256>>>(x, lnf_g, lnf_b, xn2);
    mma_gemm<false, false><<<gVc, 256, GEMM_SMEM>>>(xn2, tok2, nullptr, nullptr, logits, MM, VV, E2);

    if (do_loss) loss_kernel<<<MM, 256>>>(logits, targets, loss_ptr);
}

// round 12
// speedup vs baseline: 1.5885x; 1.0935x over previous
#include <cuda_runtime.h>
#include <cuda_fp16.h>
#include <math.h>
#include <stdint.h>

// ---------------- problem constants ----------------
#define BB 4
#define TT 1024
#define EE 768
#define HH 8
#define HS 96
#define LL 8
#define VV 32000
#define FF 3072            // 4*E
#define MM (BB*TT)         // 4096 rows
#define E2 (2*EE)          // 1536 (2-term split K for E)
#define E3 (3*EE)          // 2304 (QKV output width q|k|v)
#define F2 (2*FF)          // 6144

typedef __half fp16;

// ---------------- scratch (device globals; no allocation allowed) ----------------
__device__ __align__(256) float g_x   [(size_t)MM*EE];
__device__ __align__(256) fp16  g_xn2 [(size_t)MM*E2];
__device__ __align__(256) fp16  g_qkv2[(size_t)MM*2*E3];       // [M][hi(2304) | lo(2304)]
__device__ __align__(256) fp16  g_att2[(size_t)MM*E2];
__device__ __align__(256) fp16  g_h42 [(size_t)MM*F2];

// weights, B-layout [2K rows][N cols], both K-blocks = round(W) fp16
__device__ __align__(256) fp16  g_wqkv2[(size_t)LL*E2*E3];
__device__ __align__(256) fp16  g_wo2  [(size_t)LL*E2*EE];
__device__ __align__(256) fp16  g_w12  [(size_t)LL*E2*FF];
__device__ __align__(256) fp16  g_w22  [(size_t)LL*F2*EE];
__device__ __align__(256) fp16  g_tok2 [(size_t)EE*VV];        // 1-term lm-head B: [768][32000]

__device__ __align__(256) float g_logits_scratch[(size_t)MM*VV];

// ---------------- helpers ----------------
__device__ __forceinline__ void split2h(float v, fp16& hi, fp16& lo) {
    hi = __float2half(v);
    lo = __float2half(v - __half2float(hi));
}
__device__ __forceinline__ uint32_t pack2h(fp16 a, fp16 b) {
    uint16_t x = *(uint16_t*)&a, y = *(uint16_t*)&b;
    return (uint32_t)x | ((uint32_t)y << 16);
}
__device__ __forceinline__ void cp16(void* dst_smem, const void* src_gmem) {
    uint32_t s = (uint32_t)__cvta_generic_to_shared(dst_smem);
    asm volatile("cp.async.cg.shared.global [%0], [%1], 16;\n" :: "r"(s), "l"(src_gmem));
}
__device__ __forceinline__ void cp_commit() { asm volatile("cp.async.commit_group;\n" ::: "memory"); }
__device__ __forceinline__ void cp_wait1()  { asm volatile("cp.async.wait_group 1;\n" ::: "memory"); }

__device__ __forceinline__ void ldmA4(uint32_t* a, const void* p) {
    uint32_t s = (uint32_t)__cvta_generic_to_shared(p);
    asm volatile("ldmatrix.sync.aligned.m8n8.x4.shared.b16 {%0,%1,%2,%3}, [%4];"
                 : "=r"(a[0]), "=r"(a[1]), "=r"(a[2]), "=r"(a[3]) : "r"(s));
}
__device__ __forceinline__ void ldmB4t(uint32_t* b, const void* p) {
    uint32_t s = (uint32_t)__cvta_generic_to_shared(p);
    asm volatile("ldmatrix.sync.aligned.m8n8.x4.trans.shared.b16 {%0,%1,%2,%3}, [%4];"
                 : "=r"(b[0]), "=r"(b[1]), "=r"(b[2]), "=r"(b[3]) : "r"(s));
}
__device__ __forceinline__ void mma16816h(float* c, const uint32_t* a, const uint32_t* b) {
    asm volatile(
        "mma.sync.aligned.m16n8k16.row.col.f32.f16.f16.f32 "
        "{%0,%1,%2,%3},{%4,%5,%6,%7},{%8,%9},{%0,%1,%2,%3};"
        : "+f"(c[0]), "+f"(c[1]), "+f"(c[2]), "+f"(c[3])
        : "r"(a[0]), "r"(a[1]), "r"(a[2]), "r"(a[3]), "r"(b[0]), "r"(b[1]));
}

// ---------------- batched weight conversion (all layers, all 6 tensors) -------------
// W[K,N] fp32 -> B [2K][N], both row blocks = round(W).
__global__ void convert_all_kernel(const float* __restrict__ Wq, const float* __restrict__ Wk,
                                   const float* __restrict__ Wv, const float* __restrict__ Wo,
                                   const float* __restrict__ W1, const float* __restrict__ W2)
{
    const int l = blockIdx.y / 6, seg = blockIdx.y % 6;
    const float* W; fp16* out; int K, N, pitch, colOff;
    switch (seg) {
        case 0: W = Wq + (size_t)l*EE*EE; out = g_wqkv2 + (size_t)l*E2*E3; K=EE; N=EE; pitch=E3; colOff=0;    break;
        case 1: W = Wk + (size_t)l*EE*EE; out = g_wqkv2 + (size_t)l*E2*E3; K=EE; N=EE; pitch=E3; colOff=EE;   break;
        case 2: W = Wv + (size_t)l*EE*EE; out = g_wqkv2 + (size_t)l*E2*E3; K=EE; N=EE; pitch=E3; colOff=2*EE; break;
        case 3: W = Wo + (size_t)l*EE*EE; out = g_wo2   + (size_t)l*E2*EE; K=EE; N=EE; pitch=EE; colOff=0;    break;
        case 4: W = W1 + (size_t)l*EE*FF; out = g_w12   + (size_t)l*E2*FF; K=EE; N=FF; pitch=FF; colOff=0;    break;
        default:W = W2 + (size_t)l*FF*EE; out = g_w22   + (size_t)l*F2*EE; K=FF; N=EE; pitch=EE; colOff=0;    break;
    }
    int i = blockIdx.x * 256 + threadIdx.x;
    if (i >= K * N) return;
    int k = i / N, n = i % N;
    fp16 hi = __float2half(W[i]);
    out[(size_t)k * pitch + colOff + n]       = hi;
    out[(size_t)(K + k) * pitch + colOff + n] = hi;
}

// Contract (layer GEMMs): A segments [hi | lo] (fp16, exact), B row-blocks [hi; hi]
//   C = A * round(B); error = B-rounding only (~2^-11)
// lm-head: 1-term A (hi only), 1-term B -> adds one non-compounding xn-rounding term.

// ---------------- tok transpose: out[EE, V] from tok[V, E] (1-term B) -------------
__global__ void convert_tok_kernel(const float* __restrict__ tok, fp16* __restrict__ out)
{
    __shared__ float t[32][33];
    int k0 = blockIdx.x * 32, n0 = blockIdx.y * 32;
    int tx = threadIdx.x, ty = threadIdx.y;
    t[ty][tx] = tok[(size_t)(n0 + ty) * EE + k0 + tx];
    __syncthreads();
    fp16 hi = __float2half(t[tx][ty]);
    size_t k = k0 + ty, n = n0 + tx;
    out[k * VV + n] = hi;
}

// ---------------- embedding ----------------
__global__ void embed_kernel(const int* __restrict__ idx,
                             const float* __restrict__ tok,
                             const float* __restrict__ pos,
                             float* __restrict__ x)
{
    size_t i = (size_t)blockIdx.x * blockDim.x + threadIdx.x;
    if (i >= (size_t)MM * EE) return;
    int e  = (int)(i % EE);
    int bt = (int)(i / EE);
    int t  = bt % TT;
    x[i] = tok[(size_t)idx[bt] * EE + e] + pos[(size_t)t * EE + e];
}

// ---------------- layernorm, warp-per-row -> A-side fp16 [row, 2E]: [hi | lo] -------
// grid MM/8, block 256 (8 warps). Each lane handles 24 elems (6 x float4).
__global__ void ln_split_kernel(const float* __restrict__ x,
                                const float* __restrict__ g,
                                const float* __restrict__ b,
                                fp16* __restrict__ out)
{
    const int warp = threadIdx.x >> 5, lane = threadIdx.x & 31;
    const int row = blockIdx.x * 8 + warp;
    const float* xr = x + (size_t)row * EE;

    float4 v[6];
    float s = 0.f, s2 = 0.f;
#pragma unroll
    for (int j = 0; j < 6; j++) {
        v[j] = *(const float4*)&xr[(j * 32 + lane) * 4];
        s  += v[j].x + v[j].y + v[j].z + v[j].w;
        s2 += v[j].x * v[j].x + v[j].y * v[j].y + v[j].z * v[j].z + v[j].w * v[j].w;
    }
#pragma unroll
    for (int o = 16; o > 0; o >>= 1) {
        s  += __shfl_xor_sync(0xffffffffu, s,  o);
        s2 += __shfl_xor_sync(0xffffffffu, s2, o);
    }
    const float mean = s * (1.f / EE);
    const float var  = s2 * (1.f / EE) - mean * mean;
    const float inv  = rsqrtf(var + 1e-5f);

    fp16* orow = out + (size_t)row * E2;
#pragma unroll
    for (int j = 0; j < 6; j++) {
        const int e0 = (j * 32 + lane) * 4;
        float4 gg = *(const float4*)&g[e0];
        float4 bb = *(const float4*)&b[e0];
        float f0 = (v[j].x - mean) * inv * gg.x + bb.x;
        float f1 = (v[j].y - mean) * inv * gg.y + bb.y;
        float f2 = (v[j].z - mean) * inv * gg.z + bb.z;
        float f3 = (v[j].w - mean) * inv * gg.w + bb.w;
        fp16 h0, l0, h1, l1, h2, l2, h3, l3;
        split2h(f0, h0, l0); split2h(f1, h1, l1);
        split2h(f2, h2, l2); split2h(f3, h3, l3);
        uint2 hv; hv.x = pack2h(h0, h1); hv.y = pack2h(h2, h3);
        uint2 lv; lv.x = pack2h(l0, l1); lv.y = pack2h(l2, l3);
        *(uint2*)&orow[e0]      = hv;
        *(uint2*)&orow[EE + e0] = lv;
    }
}

// ---------------- tensor-core GEMM: C[M,N] = A[M,K2] @ B[K2,N] (fp16, fp32 acc) --------
// Block 128x128, warp 64x32, K-tile 64, 2-stage cp.async, 2 CTAs/SM, persistent col-major.
// lda = A row pitch in elements (>= K2). Dynamic smem = 73728 B.
template<bool GELU, bool SPLIT>
__global__ void __launch_bounds__(256, 2)
mma_gemm(const fp16* __restrict__ A, const fp16* __restrict__ B,
         const float* __restrict__ bias, const float* __restrict__ res,
         void* __restrict__ Cv, int M, int N, int K2, int lda)
{
    extern __shared__ char dynsm[];
    fp16* As = (fp16*)dynsm;             // [2][128*72]
    fp16* Bs = (fp16*)dynsm + 18432;     // [2][64*144]

    const int tid  = threadIdx.x;
    const int lane = tid & 31;
    const int warp = tid >> 5;
    const int wm   = warp & 1;
    const int wn   = warp >> 1;

    const int nRowT = M >> 7;
    const int nColT = N >> 7;
    const int nTiles = nRowT * nColT;
    const int ntk = K2 >> 6;

    for (int tile = blockIdx.x; tile < nTiles; tile += gridDim.x) {
        const int col0 = (tile / nRowT) * 128;
        const int row0 = (tile % nRowT) * 128;

        float acc[4][4][4];
#pragma unroll
        for (int i = 0; i < 4; i++)
#pragma unroll
            for (int j = 0; j < 4; j++)
#pragma unroll
                for (int r = 0; r < 4; r++) acc[i][j][r] = 0.f;

        auto load_tile = [&](int s, int k0) {
#pragma unroll
            for (int i = 0; i < 4; i++) {
                int idx = tid + i * 256;
                int r = idx >> 3, c = (idx & 7) * 8;
                cp16(&As[s * 9216 + r * 72 + c], &A[(size_t)(row0 + r) * lda + k0 + c]);
            }
#pragma unroll
            for (int i = 0; i < 4; i++) {
                int idx = tid + i * 256;
                int r = idx >> 4, c = (idx & 15) * 8;
                cp16(&Bs[s * 9216 + r * 144 + c], &B[(size_t)(k0 + r) * N + col0 + c]);
            }
        };

        __syncthreads();
        load_tile(0, 0);
        cp_commit();

        for (int t = 0; t < ntk; t++) {
            if (t + 1 < ntk) load_tile((t + 1) & 1, (t + 1) * 64);
            cp_commit();
            cp_wait1();
            __syncthreads();
            const int s = t & 1;

#pragma unroll
            for (int kk = 0; kk < 64; kk += 16) {
                uint32_t a[4][4], b[2][4];
#pragma unroll
                for (int mi = 0; mi < 4; mi++)
                    ldmA4(a[mi], &As[s * 9216 + (wm * 64 + mi * 16 + (lane & 15)) * 72 + kk + (lane >> 4) * 8]);
#pragma unroll
                for (int nj = 0; nj < 2; nj++)
                    ldmB4t(b[nj], &Bs[s * 9216 + (kk + (lane & 15)) * 144 + wn * 32 + nj * 16 + (lane >> 4) * 8]);
#pragma unroll
                for (int mi = 0; mi < 4; mi++) {
                    mma16816h(acc[mi][0], a[mi], b[0]);
                    mma16816h(acc[mi][1], a[mi], b[0] + 2);
                    mma16816h(acc[mi][2], a[mi], b[1]);
                    mma16816h(acc[mi][3], a[mi], b[1] + 2);
                }
            }
            __syncthreads();
        }

        // ---- epilogue ----
        const int gid = lane >> 2, tig = lane & 3;
#pragma unroll
        for (int mi = 0; mi < 4; mi++) {
#pragma unroll
            for (int ni = 0; ni < 4; ni++) {
                int gr = row0 + wm * 64 + mi * 16 + gid;
                int gc = col0 + wn * 32 + ni * 8 + tig * 2;
#pragma unroll
                for (int half = 0; half < 2; half++) {
                    int r = gr + half * 8;
#pragma unroll
                    for (int cc = 0; cc < 2; cc++) {
                        float c = acc[mi][ni][half * 2 + cc];
                        int col = gc + cc;
                        if (bias) c += bias[col];
                        if (GELU) c = 0.5f * c * (1.f + erff(c * 0.70710678118654752f));
                        if (SPLIT) {
                            fp16 hi, lo; split2h(c, hi, lo);
                            fp16* C = (fp16*)Cv;
                            size_t base = (size_t)r * (2 * N) + col;
                            C[base] = hi; C[base + N] = lo;
                        } else {
                            float* C = (float*)Cv;
                            if (res) c += res[(size_t)r * N + col];
                            C[(size_t)r * N + col] = c;
                        }
                    }
                }
            }
        }
    }
}

// ---------------- fp16 flash attention (unchanged from R10, works) ----------------
__global__ void __launch_bounds__(256)
attn_mma_kernel(const fp16* __restrict__ qkv2, fp16* __restrict__ att2)
{
    extern __shared__ char dynsm[];
    fp16* Qs = (fp16*)dynsm;
    fp16* Ks = (fp16*)(dynsm + 51200);
    fp16* Vs = (fp16*)(dynsm + 65024);
    fp16* Ps = (fp16*)(dynsm + 78336);

    const int qb0  = blockIdx.x * 128;
    const int h    = blockIdx.y;
    const int b    = blockIdx.z;
    const int tid  = threadIdx.x;
    const int lane = tid & 31;
    const int w    = tid >> 5;
    const int gid  = lane >> 2, tig = lane & 3;

    const size_t NQ = 2 * E3;
    const size_t rowbase = (size_t)(b * TT) * NQ;
    const int qoff = h * HS, koff = EE + h * HS, voff = 2 * EE + h * HS;

    for (int i = tid; i < 128 * 12; i += 256) {
        int r = i / 12, e0 = (i % 12) * 8;
        const size_t g = rowbase + (size_t)(qb0 + r) * NQ;
        *(uint4*)&Qs[r * 200 + e0]      = *(const uint4*)&qkv2[g + qoff + e0];
        *(uint4*)&Qs[r * 200 + 96 + e0] = *(const uint4*)&qkv2[g + E3 + qoff + e0];
    }

    float o[12][4];
#pragma unroll
    for (int i = 0; i < 12; i++)
#pragma unroll
        for (int j = 0; j < 4; j++) o[i][j] = 0.f;
    float mrow0 = -1e30f, mrow1 = -1e30f, lrow0 = 0.f, lrow1 = 0.f;

    const float scale = 0.10206207261596577f;
    const int nchunks = qb0 / 64 + 2;

    for (int ch = 0; ch < nchunks; ch++) {
        const int c0 = ch * 64;
        __syncthreads();
        for (int i = tid; i < 64 * 12; i += 256) {
            int key = i / 12, e0 = (i % 12) * 8;
            const size_t g = rowbase + (size_t)(c0 + key) * NQ;
            uint4 khiv = *(const uint4*)&qkv2[g + koff + e0];
            const fp16* kh = (const fp16*)&khiv;
#pragma unroll
            for (int j = 0; j < 8; j++)
                Ks[(e0 + j) * 72 + key] = kh[j];
            *(uint4*)&Vs[key * 104 + e0] = *(const uint4*)&qkv2[g + voff + e0];
        }
        __syncthreads();

        float sacc[8][4];
#pragma unroll
        for (int i = 0; i < 8; i++)
#pragma unroll
            for (int j = 0; j < 4; j++) sacc[i][j] = 0.f;

#pragma unroll
        for (int sgi = 0; sgi < 2; sgi++) {
            const int qs0 = sgi * 96;
#pragma unroll
            for (int kk = 0; kk < 96; kk += 16) {
                uint32_t a[4];
                ldmA4(a, &Qs[(w * 16 + (lane & 15)) * 200 + qs0 + kk + (lane >> 4) * 8]);
#pragma unroll
                for (int nt = 0; nt < 8; nt += 2) {
                    uint32_t bb[4];
                    ldmB4t(bb, &Ks[(kk + (lane & 15)) * 72 + nt * 8 + (lane >> 4) * 8]);
                    mma16816h(sacc[nt],     a, bb);
                    mma16816h(sacc[nt + 1], a, bb + 2);
                }
            }
        }

        const int rg0 = qb0 + w * 16 + gid;
        const bool need_mask = (c0 + 64 > qb0);
        float cm0 = -1e30f, cm1 = -1e30f;
#pragma unroll
        for (int nt = 0; nt < 8; nt++) {
#pragma unroll
            for (int e = 0; e < 4; e++) {
                float s = sacc[nt][e] * scale;
                if (need_mask) {
                    int col = c0 + nt * 8 + tig * 2 + (e & 1);
                    int row = rg0 + (e >> 1) * 8;
                    if (col > row) s = -1e30f;
                }
                sacc[nt][e] = s;
                if (e < 2) cm0 = fmaxf(cm0, s); else cm1 = fmaxf(cm1, s);
            }
        }
        cm0 = fmaxf(cm0, __shfl_xor_sync(0xffffffffu, cm0, 1));
        cm0 = fmaxf(cm0, __shfl_xor_sync(0xffffffffu, cm0, 2));
        cm1 = fmaxf(cm1, __shfl_xor_sync(0xffffffffu, cm1, 1));
        cm1 = fmaxf(cm1, __shfl_xor_sync(0xffffffffu, cm1, 2));

        const float mn0 = fmaxf(mrow0, cm0), mn1 = fmaxf(mrow1, cm1);
        const float al0 = __expf(mrow0 - mn0), al1 = __expf(mrow1 - mn1);
        float cs0 = 0.f, cs1 = 0.f;
#pragma unroll
        for (int nt = 0; nt < 8; nt++) {
            float p0 = __expf(sacc[nt][0] - mn0), p1 = __expf(sacc[nt][1] - mn0);
            float p2 = __expf(sacc[nt][2] - mn1), p3 = __expf(sacc[nt][3] - mn1);
            cs0 += p0 + p1; cs1 += p2 + p3;
            int colb = nt * 8 + tig * 2;
            *(uint32_t*)&Ps[(w * 16 + gid) * 72 + colb]     = pack2h(__float2half(p0), __float2half(p1));
            *(uint32_t*)&Ps[(w * 16 + gid + 8) * 72 + colb] = pack2h(__float2half(p2), __float2half(p3));
        }
        cs0 += __shfl_xor_sync(0xffffffffu, cs0, 1);
        cs0 += __shfl_xor_sync(0xffffffffu, cs0, 2);
        cs1 += __shfl_xor_sync(0xffffffffu, cs1, 1);
        cs1 += __shfl_xor_sync(0xffffffffu, cs1, 2);

        lrow0 = lrow0 * al0 + cs0; lrow1 = lrow1 * al1 + cs1;
        mrow0 = mn0; mrow1 = mn1;
#pragma unroll
        for (int nt = 0; nt < 12; nt++) {
            o[nt][0] *= al0; o[nt][1] *= al0; o[nt][2] *= al1; o[nt][3] *= al1;
        }
        __syncwarp();

#pragma unroll
        for (int kk = 0; kk < 64; kk += 16) {
            uint32_t a[4];
            ldmA4(a, &Ps[(w * 16 + (lane & 15)) * 72 + kk + (lane >> 4) * 8]);
#pragma unroll
            for (int nt = 0; nt < 12; nt += 2) {
                uint32_t bb[4];
                ldmB4t(bb, &Vs[(kk + (lane & 15)) * 104 + nt * 8 + (lane >> 4) * 8]);
                mma16816h(o[nt],     a, bb);
                mma16816h(o[nt + 1], a, bb + 2);
            }
        }
    }

    const float iv0 = 1.f / lrow0, iv1 = 1.f / lrow1;
#pragma unroll
    for (int nt = 0; nt < 12; nt++) {
        int d = h * HS + nt * 8 + tig * 2;
        {
            size_t orow = (size_t)(b * TT + qb0 + w * 16 + gid) * E2;
            float v0 = o[nt][0] * iv0, v1 = o[nt][1] * iv0;
            fp16 h0, l0, h1, l1; split2h(v0, h0, l0); split2h(v1, h1, l1);
            *(uint32_t*)&att2[orow + d]      = pack2h(h0, h1);
            *(uint32_t*)&att2[orow + EE + d] = pack2h(l0, l1);
        }
        {
            size_t orow = (size_t)(b * TT + qb0 + w * 16 + gid + 8) * E2;
            float v0 = o[nt][2] * iv1, v1 = o[nt][3] * iv1;
            fp16 h0, l0, h1, l1; split2h(v0, h0, l0); split2h(v1, h1, l1);
            *(uint32_t*)&att2[orow + d]      = pack2h(h0, h1);
            *(uint32_t*)&att2[orow + EE + d] = pack2h(l0, l1);
        }
    }
}

// ---------------- loss (single pass, online logsumexp, float4 reads) ---------------
__global__ void loss_zero_kernel(float* loss) { *loss = 0.f; }

__global__ void loss_kernel(const float* __restrict__ logits,
                            const int* __restrict__ targets,
                            float* __restrict__ loss)
{
    const int row = blockIdx.x;
    const int tid = threadIdx.x;   // 256
    const float* lr = logits + (size_t)row * VV;

    float m = -1e30f, s = 0.f;
    for (int j4 = tid; j4 < VV / 4; j4 += 256) {
        float4 f = *(const float4*)&lr[j4 * 4];
        float vals[4] = {f.x, f.y, f.z, f.w};
#pragma unroll
        for (int q = 0; q < 4; q++) {
            float v = vals[q];
            if (v > m) { s = s * __expf(m - v) + 1.f; m = v; }
            else       { s += __expf(v - m); }
        }
    }
    __shared__ float rm[256], rs[256];
    rm[tid] = m; rs[tid] = s; __syncthreads();
    for (int o = 128; o > 0; o >>= 1) {
        if (tid < o) {
            float m2 = rm[tid + o], s2 = rs[tid + o];
            float mm = fmaxf(rm[tid], m2);
            rs[tid] = rs[tid] * __expf(rm[tid] - mm) + s2 * __expf(m2 - mm);
            rm[tid] = mm;
        }
        __syncthreads();
    }
    if (tid == 0) {
        float lp = lr[targets[row]] - rm[0] - logf(rs[0]);
        atomicAdd(loss, -lp * (1.f / (float)MM));
    }
}

// ---------------- launch ----------------
extern "C" void kernel_launch(void* const* d_in, const int* in_sizes, int n_in,
                              void* d_out, int out_size)
{
    const int*   idx     = (const int*)  d_in[0];
    const int*   targets = (const int*)  d_in[1];
    const float* tok     = (const float*)d_in[2];
    const float* pos     = (const float*)d_in[3];
    const float* Wq      = (const float*)d_in[4];
    const float* Wk      = (const float*)d_in[5];
    const float* Wv      = (const float*)d_in[6];
    const float* Wo      = (const float*)d_in[7];
    const float* bo      = (const float*)d_in[8];
    const float* ln1_g   = (const float*)d_in[9];
    const float* ln1_b   = (const float*)d_in[10];
    const float* ln2_g   = (const float*)d_in[11];
    const float* ln2_b   = (const float*)d_in[12];
    const float* W1      = (const float*)d_in[13];
    const float* b1      = (const float*)d_in[14];
    const float* W2      = (const float*)d_in[15];
    const float* b2      = (const float*)d_in[16];
    const float* lnf_g   = (const float*)d_in[17];
    const float* lnf_b   = (const float*)d_in[18];

    float *x, *lg_scratch;
    fp16 *xn2, *qkv2, *att2, *h42, *wqkv2, *wo2, *w12, *w22, *tok2;
    cudaGetSymbolAddress((void**)&x,    g_x);
    cudaGetSymbolAddress((void**)&xn2,  g_xn2);
    cudaGetSymbolAddress((void**)&qkv2, g_qkv2);
    cudaGetSymbolAddress((void**)&att2, g_att2);
    cudaGetSymbolAddress((void**)&h42,  g_h42);
    cudaGetSymbolAddress((void**)&wqkv2,g_wqkv2);
    cudaGetSymbolAddress((void**)&wo2,  g_wo2);
    cudaGetSymbolAddress((void**)&w12,  g_w12);
    cudaGetSymbolAddress((void**)&w22,  g_w22);
    cudaGetSymbolAddress((void**)&tok2, g_tok2);
    cudaGetSymbolAddress((void**)&lg_scratch, g_logits_scratch);

    const int GEMM_SMEM = 73728;
    const int ATTN_SMEM = 96768;
    cudaFuncSetAttribute(mma_gemm<false,true >, cudaFuncAttributeMaxDynamicSharedMemorySize, GEMM_SMEM);
    cudaFuncSetAttribute(mma_gemm<true ,true >, cudaFuncAttributeMaxDynamicSharedMemorySize, GEMM_SMEM);
    cudaFuncSetAttribute(mma_gemm<false,false>, cudaFuncAttributeMaxDynamicSharedMemorySize, GEMM_SMEM);
    cudaFuncSetAttribute(attn_mma_kernel, cudaFuncAttributeMaxDynamicSharedMemorySize, ATTN_SMEM);

    const bool out_holds_logits = ((long long)out_size >= (long long)MM * VV);
    float* logits = out_holds_logits ? (float*)d_out : lg_scratch;
    float* loss_ptr = out_holds_logits ? ((float*)d_out + (size_t)MM * VV)
                                       : (float*)d_out;
    const bool do_loss = (!out_holds_logits || (long long)out_size > (long long)MM * VV);

    convert_all_kernel<<<dim3(9216, 48), 256>>>(Wq, Wk, Wv, Wo, W1, W2);
    convert_tok_kernel<<<dim3(EE / 32, VV / 32), dim3(32, 32)>>>(tok, tok2);
    {
        size_t n = (size_t)MM * EE;
        embed_kernel<<<(unsigned)((n + 255) / 256), 256>>>(idx, tok, pos, x);
    }
    if (do_loss) loss_zero_kernel<<<1, 1>>>(loss_ptr);

    const int MAXCTA = 296;   // 2 CTAs/SM
    auto pgrid = [&](int N) { int t = (MM / 128) * (N / 128); return t < MAXCTA ? t : MAXCTA; };
    const int gQKV = pgrid(E3);
    const int gEc  = pgrid(EE);
    const int gFc  = pgrid(FF);
    const int gVc  = pgrid(VV);
    const int LN_GRID = MM / 8;

    for (int l = 0; l < LL; l++) {
        ln_split_kernel<<<LN_GRID, 256>>>(x, ln1_g + (size_t)l * EE, ln1_b + (size_t)l * EE, xn2);
        mma_gemm<false, true><<<gQKV, 256, GEMM_SMEM>>>(xn2, wqkv2 + (size_t)l * E2 * E3,
                                                        nullptr, nullptr, qkv2, MM, E3, E2, E2);
        attn_mma_kernel<<<dim3(TT / 128, HH, BB), 256, ATTN_SMEM>>>(qkv2, att2);
        mma_gemm<false, false><<<gEc, 256, GEMM_SMEM>>>(att2, wo2 + (size_t)l * E2 * EE,
                                                        bo + (size_t)l * EE, x, x, MM, EE, E2, E2);
        ln_split_kernel<<<LN_GRID, 256>>>(x, ln2_g + (size_t)l * EE, ln2_b + (size_t)l * EE, xn2);
        mma_gemm<true, true><<<gFc, 256, GEMM_SMEM>>>(xn2, w12 + (size_t)l * E2 * FF,
                                                      b1 + (size_t)l * FF, nullptr, h42, MM, FF, E2, E2);
        mma_gemm<false, false><<<gEc, 256, GEMM_SMEM>>>(h42, w22 + (size_t)l * F2 * EE,
                                                        b2 + (size_t)l * EE, x, x, MM, EE, F2, F2);
    }

    ln_split_kernel<<<LN_GRID, 256>>>(x, lnf_g, lnf_b, xn2);
    // lm-head: 1-term A (hi segment of xn2, pitch E2), 1-term B
    mma_gemm<false, false><<<gVc, 256, GEMM_SMEM>>>(xn2, tok2, nullptr, nullptr,
                                                    logits, MM, VV, EE, E2);

    if (do_loss) loss_kernel<<<MM, 256>>>(logits, targets, loss_ptr);
}

// round 13
// speedup vs baseline: 1.9488x; 1.2268x over previous
#include <cuda_runtime.h>
#include <cuda_fp16.h>
#include <math.h>
#include <stdint.h>

// ---------------- problem constants ----------------
#define BB 4
#define TT 1024
#define EE 768
#define HH 8
#define HS 96
#define LL 8
#define VV 32000
#define FF 3072            // 4*E
#define MM (BB*TT)         // 4096 rows
#define E2 (2*EE)          // 1536 (2-term split K for E)
#define E3 (3*EE)          // 2304 (QKV output width q|k|v)

typedef __half fp16;

// ---------------- scratch (device globals; no allocation allowed) ----------------
__device__ __align__(256) float g_x   [(size_t)MM*EE];
__device__ __align__(256) fp16  g_xn2 [(size_t)MM*E2];
__device__ __align__(256) fp16  g_qkv2[(size_t)MM*2*E3];       // [M][hi(2304) | lo(2304)]
__device__ __align__(256) fp16  g_att2[(size_t)MM*E2];
__device__ __align__(256) fp16  g_h42 [(size_t)MM*FF];         // 1-term h4

// weights: wqkv/wo/w1 duplicated [2K rows][N]; w2 single [FF rows][EE]; tok single [EE rows][VV]
__device__ __align__(256) fp16  g_wqkv2[(size_t)LL*E2*E3];
__device__ __align__(256) fp16  g_wo2  [(size_t)LL*E2*EE];
__device__ __align__(256) fp16  g_w12  [(size_t)LL*E2*FF];
__device__ __align__(256) fp16  g_w22  [(size_t)LL*FF*EE];
__device__ __align__(256) fp16  g_tok2 [(size_t)EE*VV];

__device__ __align__(256) float g_logits_scratch[(size_t)MM*VV];

// ---------------- helpers ----------------
__device__ __forceinline__ void split2h(float v, fp16& hi, fp16& lo) {
    hi = __float2half(v);
    lo = __float2half(v - __half2float(hi));
}
__device__ __forceinline__ uint32_t pack2h(fp16 a, fp16 b) {
    uint16_t x = *(uint16_t*)&a, y = *(uint16_t*)&b;
    return (uint32_t)x | ((uint32_t)y << 16);
}
__device__ __forceinline__ void cp16(void* dst_smem, const void* src_gmem) {
    uint32_t s = (uint32_t)__cvta_generic_to_shared(dst_smem);
    asm volatile("cp.async.cg.shared.global [%0], [%1], 16;\n" :: "r"(s), "l"(src_gmem));
}
__device__ __forceinline__ void cp_commit() { asm volatile("cp.async.commit_group;\n" ::: "memory"); }
__device__ __forceinline__ void cp_wait1()  { asm volatile("cp.async.wait_group 1;\n" ::: "memory"); }

__device__ __forceinline__ void ldmA4(uint32_t* a, const void* p) {
    uint32_t s = (uint32_t)__cvta_generic_to_shared(p);
    asm volatile("ldmatrix.sync.aligned.m8n8.x4.shared.b16 {%0,%1,%2,%3}, [%4];"
                 : "=r"(a[0]), "=r"(a[1]), "=r"(a[2]), "=r"(a[3]) : "r"(s));
}
__device__ __forceinline__ void ldmB4t(uint32_t* b, const void* p) {
    uint32_t s = (uint32_t)__cvta_generic_to_shared(p);
    asm volatile("ldmatrix.sync.aligned.m8n8.x4.trans.shared.b16 {%0,%1,%2,%3}, [%4];"
                 : "=r"(b[0]), "=r"(b[1]), "=r"(b[2]), "=r"(b[3]) : "r"(s));
}
__device__ __forceinline__ void mma16816h(float* c, const uint32_t* a, const uint32_t* b) {
    asm volatile(
        "mma.sync.aligned.m16n8k16.row.col.f32.f16.f16.f32 "
        "{%0,%1,%2,%3},{%4,%5,%6,%7},{%8,%9},{%0,%1,%2,%3};"
        : "+f"(c[0]), "+f"(c[1]), "+f"(c[2]), "+f"(c[3])
        : "r"(a[0]), "r"(a[1]), "r"(a[2]), "r"(a[3]), "r"(b[0]), "r"(b[1]));
}

// ---------------- batched weight conversion (vectorized x4) -------------
// segs 0-4: W[K,N] -> [2K][N] (both blocks = round(W)); seg 5 (W2): single [K][N].
__global__ void convert_all_kernel(const float* __restrict__ Wq, const float* __restrict__ Wk,
                                   const float* __restrict__ Wv, const float* __restrict__ Wo,
                                   const float* __restrict__ W1, const float* __restrict__ W2)
{
    const int l = blockIdx.y / 6, seg = blockIdx.y % 6;
    const float* W; fp16* out; int K, N, pitch, colOff;
    switch (seg) {
        case 0: W = Wq + (size_t)l*EE*EE; out = g_wqkv2 + (size_t)l*E2*E3; K=EE; N=EE; pitch=E3; colOff=0;    break;
        case 1: W = Wk + (size_t)l*EE*EE; out = g_wqkv2 + (size_t)l*E2*E3; K=EE; N=EE; pitch=E3; colOff=EE;   break;
        case 2: W = Wv + (size_t)l*EE*EE; out = g_wqkv2 + (size_t)l*E2*E3; K=EE; N=EE; pitch=E3; colOff=2*EE; break;
        case 3: W = Wo + (size_t)l*EE*EE; out = g_wo2   + (size_t)l*E2*EE; K=EE; N=EE; pitch=EE; colOff=0;    break;
        case 4: W = W1 + (size_t)l*EE*FF; out = g_w12   + (size_t)l*E2*FF; K=EE; N=FF; pitch=FF; colOff=0;    break;
        default:W = W2 + (size_t)l*FF*EE; out = g_w22   + (size_t)l*FF*EE; K=FF; N=EE; pitch=EE; colOff=0;    break;
    }
    int base = (blockIdx.x * 256 + threadIdx.x) * 4;
    if (base >= K * N) return;
    int k = base / N, n = base % N;
    float4 f = *(const float4*)&W[base];
    uint2 h;
    h.x = pack2h(__float2half(f.x), __float2half(f.y));
    h.y = pack2h(__float2half(f.z), __float2half(f.w));
    *(uint2*)&out[(size_t)k * pitch + colOff + n] = h;
    if (seg != 5)
        *(uint2*)&out[(size_t)(K + k) * pitch + colOff + n] = h;
}

// Contract (2-term GEMMs): A [hi | lo] exact, B [round(W); round(W)] -> err = B-rounding only.
// W2 & lm-head: 1-term A, 1-term B -> adds one A-rounding term (~2.8e-4, weakly compounding).

// ---------------- tok transpose: out[EE, V] from tok[V, E] (1-term B) -------------
__global__ void convert_tok_kernel(const float* __restrict__ tok, fp16* __restrict__ out)
{
    __shared__ float t[32][33];
    int k0 = blockIdx.x * 32, n0 = blockIdx.y * 32;
    int tx = threadIdx.x, ty = threadIdx.y;
    t[ty][tx] = tok[(size_t)(n0 + ty) * EE + k0 + tx];
    __syncthreads();
    fp16 hi = __float2half(t[tx][ty]);
    size_t k = k0 + ty, n = n0 + tx;
    out[k * VV + n] = hi;
}

// ---------------- embedding ----------------
__global__ void embed_kernel(const int* __restrict__ idx,
                             const float* __restrict__ tok,
                             const float* __restrict__ pos,
                             float* __restrict__ x)
{
    size_t i = (size_t)blockIdx.x * blockDim.x + threadIdx.x;
    if (i >= (size_t)MM * EE) return;
    int e  = (int)(i % EE);
    int bt = (int)(i / EE);
    int t  = bt % TT;
    x[i] = tok[(size_t)idx[bt] * EE + e] + pos[(size_t)t * EE + e];
}

// ---------------- layernorm, warp-per-row -> A-side fp16 [row, 2E]: [hi | lo] -------
__global__ void ln_split_kernel(const float* __restrict__ x,
                                const float* __restrict__ g,
                                const float* __restrict__ b,
                                fp16* __restrict__ out)
{
    const int warp = threadIdx.x >> 5, lane = threadIdx.x & 31;
    const int row = blockIdx.x * 8 + warp;
    const float* xr = x + (size_t)row * EE;

    float4 v[6];
    float s = 0.f, s2 = 0.f;
#pragma unroll
    for (int j = 0; j < 6; j++) {
        v[j] = *(const float4*)&xr[(j * 32 + lane) * 4];
        s  += v[j].x + v[j].y + v[j].z + v[j].w;
        s2 += v[j].x * v[j].x + v[j].y * v[j].y + v[j].z * v[j].z + v[j].w * v[j].w;
    }
#pragma unroll
    for (int o = 16; o > 0; o >>= 1) {
        s  += __shfl_xor_sync(0xffffffffu, s,  o);
        s2 += __shfl_xor_sync(0xffffffffu, s2, o);
    }
    const float mean = s * (1.f / EE);
    const float var  = s2 * (1.f / EE) - mean * mean;
    const float inv  = rsqrtf(var + 1e-5f);

    fp16* orow = out + (size_t)row * E2;
#pragma unroll
    for (int j = 0; j < 6; j++) {
        const int e0 = (j * 32 + lane) * 4;
        float4 gg = *(const float4*)&g[e0];
        float4 bb = *(const float4*)&b[e0];
        float f0 = (v[j].x - mean) * inv * gg.x + bb.x;
        float f1 = (v[j].y - mean) * inv * gg.y + bb.y;
        float f2 = (v[j].z - mean) * inv * gg.z + bb.z;
        float f3 = (v[j].w - mean) * inv * gg.w + bb.w;
        fp16 h0, l0, h1, l1, h2, l2, h3, l3;
        split2h(f0, h0, l0); split2h(f1, h1, l1);
        split2h(f2, h2, l2); split2h(f3, h3, l3);
        uint2 hv; hv.x = pack2h(h0, h1); hv.y = pack2h(h2, h3);
        uint2 lv; lv.x = pack2h(l0, l1); lv.y = pack2h(l2, l3);
        *(uint2*)&orow[e0]      = hv;
        *(uint2*)&orow[EE + e0] = lv;
    }
}

// ---------------- tensor-core GEMM: C[M,N] = A[M,K2] @ B[K2,N] (fp16, fp32 acc) --------
// OUTMODE: 0 = fp32 (+res), 1 = split fp16 [hi|lo] pitch 2N, 2 = single fp16 pitch N.
// Block 128x128, warp 64x32, K-tile 64, 2-stage cp.async, 2 CTAs/SM, persistent col-major.
template<int OUTMODE, bool GELU>
__global__ void __launch_bounds__(256, 2)
mma_gemm(const fp16* __restrict__ A, const fp16* __restrict__ B,
         const float* __restrict__ bias, const float* __restrict__ res,
         void* __restrict__ Cv, int M, int N, int K2, int lda)
{
    extern __shared__ char dynsm[];
    fp16* As = (fp16*)dynsm;             // [2][128*72]
    fp16* Bs = (fp16*)dynsm + 18432;     // [2][64*144]

    const int tid  = threadIdx.x;
    const int lane = tid & 31;
    const int warp = tid >> 5;
    const int wm   = warp & 1;
    const int wn   = warp >> 1;

    const int nRowT = M >> 7;
    const int nColT = N >> 7;
    const int nTiles = nRowT * nColT;
    const int ntk = K2 >> 6;

    for (int tile = blockIdx.x; tile < nTiles; tile += gridDim.x) {
        const int col0 = (tile / nRowT) * 128;
        const int row0 = (tile % nRowT) * 128;

        float acc[4][4][4];
#pragma unroll
        for (int i = 0; i < 4; i++)
#pragma unroll
            for (int j = 0; j < 4; j++)
#pragma unroll
                for (int r = 0; r < 4; r++) acc[i][j][r] = 0.f;

        auto load_tile = [&](int s, int k0) {
#pragma unroll
            for (int i = 0; i < 4; i++) {
                int idx = tid + i * 256;
                int r = idx >> 3, c = (idx & 7) * 8;
                cp16(&As[s * 9216 + r * 72 + c], &A[(size_t)(row0 + r) * lda + k0 + c]);
            }
#pragma unroll
            for (int i = 0; i < 4; i++) {
                int idx = tid + i * 256;
                int r = idx >> 4, c = (idx & 15) * 8;
                cp16(&Bs[s * 9216 + r * 144 + c], &B[(size_t)(k0 + r) * N + col0 + c]);
            }
        };

        __syncthreads();
        load_tile(0, 0);
        cp_commit();

        for (int t = 0; t < ntk; t++) {
            if (t + 1 < ntk) load_tile((t + 1) & 1, (t + 1) * 64);
            cp_commit();
            cp_wait1();
            __syncthreads();
            const int s = t & 1;

#pragma unroll
            for (int kk = 0; kk < 64; kk += 16) {
                uint32_t a[4][4], b[2][4];
#pragma unroll
                for (int mi = 0; mi < 4; mi++)
                    ldmA4(a[mi], &As[s * 9216 + (wm * 64 + mi * 16 + (lane & 15)) * 72 + kk + (lane >> 4) * 8]);
#pragma unroll
                for (int nj = 0; nj < 2; nj++)
                    ldmB4t(b[nj], &Bs[s * 9216 + (kk + (lane & 15)) * 144 + wn * 32 + nj * 16 + (lane >> 4) * 8]);
#pragma unroll
                for (int mi = 0; mi < 4; mi++) {
                    mma16816h(acc[mi][0], a[mi], b[0]);
                    mma16816h(acc[mi][1], a[mi], b[0] + 2);
                    mma16816h(acc[mi][2], a[mi], b[1]);
                    mma16816h(acc[mi][3], a[mi], b[1] + 2);
                }
            }
            __syncthreads();
        }

        // ---- epilogue ----
        const int gid = lane >> 2, tig = lane & 3;
#pragma unroll
        for (int mi = 0; mi < 4; mi++) {
#pragma unroll
            for (int ni = 0; ni < 4; ni++) {
                int gr = row0 + wm * 64 + mi * 16 + gid;
                int gc = col0 + wn * 32 + ni * 8 + tig * 2;
#pragma unroll
                for (int half = 0; half < 2; half++) {
                    int r = gr + half * 8;
#pragma unroll
                    for (int cc = 0; cc < 2; cc++) {
                        float c = acc[mi][ni][half * 2 + cc];
                        int col = gc + cc;
                        if (bias) c += bias[col];
                        if (GELU) c = 0.5f * c * (1.f + erff(c * 0.70710678118654752f));
                        if (OUTMODE == 1) {
                            fp16 hi, lo; split2h(c, hi, lo);
                            fp16* C = (fp16*)Cv;
                            size_t base = (size_t)r * (2 * N) + col;
                            C[base] = hi; C[base + N] = lo;
                        } else if (OUTMODE == 2) {
                            fp16* C = (fp16*)Cv;
                            C[(size_t)r * N + col] = __float2half(c);
                        } else {
                            float* C = (float*)Cv;
                            if (res) c += res[(size_t)r * N + col];
                            C[(size_t)r * N + col] = c;
                        }
                    }
                }
            }
        }
    }
}

// ---------------- fp16 flash attention (unchanged, works) ----------------
__global__ void __launch_bounds__(256)
attn_mma_kernel(const fp16* __restrict__ qkv2, fp16* __restrict__ att2)
{
    extern __shared__ char dynsm[];
    fp16* Qs = (fp16*)dynsm;
    fp16* Ks = (fp16*)(dynsm + 51200);
    fp16* Vs = (fp16*)(dynsm + 65024);
    fp16* Ps = (fp16*)(dynsm + 78336);

    const int qb0  = blockIdx.x * 128;
    const int h    = blockIdx.y;
    const int b    = blockIdx.z;
    const int tid  = threadIdx.x;
    const int lane = tid & 31;
    const int w    = tid >> 5;
    const int gid  = lane >> 2, tig = lane & 3;

    const size_t NQ = 2 * E3;
    const size_t rowbase = (size_t)(b * TT) * NQ;
    const int qoff = h * HS, koff = EE + h * HS, voff = 2 * EE + h * HS;

    for (int i = tid; i < 128 * 12; i += 256) {
        int r = i / 12, e0 = (i % 12) * 8;
        const size_t g = rowbase + (size_t)(qb0 + r) * NQ;
        *(uint4*)&Qs[r * 200 + e0]      = *(const uint4*)&qkv2[g + qoff + e0];
        *(uint4*)&Qs[r * 200 + 96 + e0] = *(const uint4*)&qkv2[g + E3 + qoff + e0];
    }

    float o[12][4];
#pragma unroll
    for (int i = 0; i < 12; i++)
#pragma unroll
        for (int j = 0; j < 4; j++) o[i][j] = 0.f;
    float mrow0 = -1e30f, mrow1 = -1e30f, lrow0 = 0.f, lrow1 = 0.f;

    const float scale = 0.10206207261596577f;
    const int nchunks = qb0 / 64 + 2;

    for (int ch = 0; ch < nchunks; ch++) {
        const int c0 = ch * 64;
        __syncthreads();
        for (int i = tid; i < 64 * 12; i += 256) {
            int key = i / 12, e0 = (i % 12) * 8;
            const size_t g = rowbase + (size_t)(c0 + key) * NQ;
            uint4 khiv = *(const uint4*)&qkv2[g + koff + e0];
            const fp16* kh = (const fp16*)&khiv;
#pragma unroll
            for (int j = 0; j < 8; j++)
                Ks[(e0 + j) * 72 + key] = kh[j];
            *(uint4*)&Vs[key * 104 + e0] = *(const uint4*)&qkv2[g + voff + e0];
        }
        __syncthreads();

        float sacc[8][4];
#pragma unroll
        for (int i = 0; i < 8; i++)
#pragma unroll
            for (int j = 0; j < 4; j++) sacc[i][j] = 0.f;

#pragma unroll
        for (int sgi = 0; sgi < 2; sgi++) {
            const int qs0 = sgi * 96;
#pragma unroll
            for (int kk = 0; kk < 96; kk += 16) {
                uint32_t a[4];
                ldmA4(a, &Qs[(w * 16 + (lane & 15)) * 200 + qs0 + kk + (lane >> 4) * 8]);
#pragma unroll
                for (int nt = 0; nt < 8; nt += 2) {
                    uint32_t bb[4];
                    ldmB4t(bb, &Ks[(kk + (lane & 15)) * 72 + nt * 8 + (lane >> 4) * 8]);
                    mma16816h(sacc[nt],     a, bb);
                    mma16816h(sacc[nt + 1], a, bb + 2);
                }
            }
        }

        const int rg0 = qb0 + w * 16 + gid;
        const bool need_mask = (c0 + 64 > qb0);
        float cm0 = -1e30f, cm1 = -1e30f;
#pragma unroll
        for (int nt = 0; nt < 8; nt++) {
#pragma unroll
            for (int e = 0; e < 4; e++) {
                float s = sacc[nt][e] * scale;
                if (need_mask) {
                    int col = c0 + nt * 8 + tig * 2 + (e & 1);
                    int row = rg0 + (e >> 1) * 8;
                    if (col > row) s = -1e30f;
                }
                sacc[nt][e] = s;
                if (e < 2) cm0 = fmaxf(cm0, s); else cm1 = fmaxf(cm1, s);
            }
        }
        cm0 = fmaxf(cm0, __shfl_xor_sync(0xffffffffu, cm0, 1));
        cm0 = fmaxf(cm0, __shfl_xor_sync(0xffffffffu, cm0, 2));
        cm1 = fmaxf(cm1, __shfl_xor_sync(0xffffffffu, cm1, 1));
        cm1 = fmaxf(cm1, __shfl_xor_sync(0xffffffffu, cm1, 2));

        const float mn0 = fmaxf(mrow0, cm0), mn1 = fmaxf(mrow1, cm1);
        const float al0 = __expf(mrow0 - mn0), al1 = __expf(mrow1 - mn1);
        float cs0 = 0.f, cs1 = 0.f;
#pragma unroll
        for (int nt = 0; nt < 8; nt++) {
            float p0 = __expf(sacc[nt][0] - mn0), p1 = __expf(sacc[nt][1] - mn0);
            float p2 = __expf(sacc[nt][2] - mn1), p3 = __expf(sacc[nt][3] - mn1);
            cs0 += p0 + p1; cs1 += p2 + p3;
            int colb = nt * 8 + tig * 2;
            *(uint32_t*)&Ps[(w * 16 + gid) * 72 + colb]     = pack2h(__float2half(p0), __float2half(p1));
            *(uint32_t*)&Ps[(w * 16 + gid + 8) * 72 + colb] = pack2h(__float2half(p2), __float2half(p3));
        }
        cs0 += __shfl_xor_sync(0xffffffffu, cs0, 1);
        cs0 += __shfl_xor_sync(0xffffffffu, cs0, 2);
        cs1 += __shfl_xor_sync(0xffffffffu, cs1, 1);
        cs1 += __shfl_xor_sync(0xffffffffu, cs1, 2);

        lrow0 = lrow0 * al0 + cs0; lrow1 = lrow1 * al1 + cs1;
        mrow0 = mn0; mrow1 = mn1;
#pragma unroll
        for (int nt = 0; nt < 12; nt++) {
            o[nt][0] *= al0; o[nt][1] *= al0; o[nt][2] *= al1; o[nt][3] *= al1;
        }
        __syncwarp();

#pragma unroll
        for (int kk = 0; kk < 64; kk += 16) {
            uint32_t a[4];
            ldmA4(a, &Ps[(w * 16 + (lane & 15)) * 72 + kk + (lane >> 4) * 8]);
#pragma unroll
            for (int nt = 0; nt < 12; nt += 2) {
                uint32_t bb[4];
                ldmB4t(bb, &Vs[(kk + (lane & 15)) * 104 + nt * 8 + (lane >> 4) * 8]);
                mma16816h(o[nt],     a, bb);
                mma16816h(o[nt + 1], a, bb + 2);
            }
        }
    }

    const float iv0 = 1.f / lrow0, iv1 = 1.f / lrow1;
#pragma unroll
    for (int nt = 0; nt < 12; nt++) {
        int d = h * HS + nt * 8 + tig * 2;
        {
            size_t orow = (size_t)(b * TT + qb0 + w * 16 + gid) * E2;
            float v0 = o[nt][0] * iv0, v1 = o[nt][1] * iv0;
            fp16 h0, l0, h1, l1; split2h(v0, h0, l0); split2h(v1, h1, l1);
            *(uint32_t*)&att2[orow + d]      = pack2h(h0, h1);
            *(uint32_t*)&att2[orow + EE + d] = pack2h(l0, l1);
        }
        {
            size_t orow = (size_t)(b * TT + qb0 + w * 16 + gid + 8) * E2;
            float v0 = o[nt][2] * iv1, v1 = o[nt][3] * iv1;
            fp16 h0, l0, h1, l1; split2h(v0, h0, l0); split2h(v1, h1, l1);
            *(uint32_t*)&att2[orow + d]      = pack2h(h0, h1);
            *(uint32_t*)&att2[orow + EE + d] = pack2h(l0, l1);
        }
    }
}

// ---------------- loss (single pass, online logsumexp, float4 reads) ---------------
__global__ void loss_zero_kernel(float* loss) { *loss = 0.f; }

__global__ void loss_kernel(const float* __restrict__ logits,
                            const int* __restrict__ targets,
                            float* __restrict__ loss)
{
    const int row = blockIdx.x;
    const int tid = threadIdx.x;   // 256
    const float* lr = logits + (size_t)row * VV;

    float m = -1e30f, s = 0.f;
    for (int j4 = tid; j4 < VV / 4; j4 += 256) {
        float4 f = *(const float4*)&lr[j4 * 4];
        float vals[4] = {f.x, f.y, f.z, f.w};
#pragma unroll
        for (int q = 0; q < 4; q++) {
            float v = vals[q];
            if (v > m) { s = s * __expf(m - v) + 1.f; m = v; }
            else       { s += __expf(v - m); }
        }
    }
    __shared__ float rm[256], rs[256];
    rm[tid] = m; rs[tid] = s; __syncthreads();
    for (int o = 128; o > 0; o >>= 1) {
        if (tid < o) {
            float m2 = rm[tid + o], s2 = rs[tid + o];
            float mm = fmaxf(rm[tid], m2);
            rs[tid] = rs[tid] * __expf(rm[tid] - mm) + s2 * __expf(m2 - mm);
            rm[tid] = mm;
        }
        __syncthreads();
    }
    if (tid == 0) {
        float lp = lr[targets[row]] - rm[0] - logf(rs[0]);
        atomicAdd(loss, -lp * (1.f / (float)MM));
    }
}

// ---------------- launch ----------------
extern "C" void kernel_launch(void* const* d_in, const int* in_sizes, int n_in,
                              void* d_out, int out_size)
{
    const int*   idx     = (const int*)  d_in[0];
    const int*   targets = (const int*)  d_in[1];
    const float* tok     = (const float*)d_in[2];
    const float* pos     = (const float*)d_in[3];
    const float* Wq      = (const float*)d_in[4];
    const float* Wk      = (const float*)d_in[5];
    const float* Wv      = (const float*)d_in[6];
    const float* Wo      = (const float*)d_in[7];
    const float* bo      = (const float*)d_in[8];
    const float* ln1_g   = (const float*)d_in[9];
    const float* ln1_b   = (const float*)d_in[10];
    const float* ln2_g   = (const float*)d_in[11];
    const float* ln2_b   = (const float*)d_in[12];
    const float* W1      = (const float*)d_in[13];
    const float* b1      = (const float*)d_in[14];
    const float* W2      = (const float*)d_in[15];
    const float* b2      = (const float*)d_in[16];
    const float* lnf_g   = (const float*)d_in[17];
    const float* lnf_b   = (const float*)d_in[18];

    float *x, *lg_scratch;
    fp16 *xn2, *qkv2, *att2, *h42, *wqkv2, *wo2, *w12, *w22, *tok2;
    cudaGetSymbolAddress((void**)&x,    g_x);
    cudaGetSymbolAddress((void**)&xn2,  g_xn2);
    cudaGetSymbolAddress((void**)&qkv2, g_qkv2);
    cudaGetSymbolAddress((void**)&att2, g_att2);
    cudaGetSymbolAddress((void**)&h42,  g_h42);
    cudaGetSymbolAddress((void**)&wqkv2,g_wqkv2);
    cudaGetSymbolAddress((void**)&wo2,  g_wo2);
    cudaGetSymbolAddress((void**)&w12,  g_w12);
    cudaGetSymbolAddress((void**)&w22,  g_w22);
    cudaGetSymbolAddress((void**)&tok2, g_tok2);
    cudaGetSymbolAddress((void**)&lg_scratch, g_logits_scratch);

    const int GEMM_SMEM = 73728;
    const int ATTN_SMEM = 96768;
    cudaFuncSetAttribute(mma_gemm<1,false>, cudaFuncAttributeMaxDynamicSharedMemorySize, GEMM_SMEM);
    cudaFuncSetAttribute(mma_gemm<2,true >, cudaFuncAttributeMaxDynamicSharedMemorySize, GEMM_SMEM);
    cudaFuncSetAttribute(mma_gemm<0,false>, cudaFuncAttributeMaxDynamicSharedMemorySize, GEMM_SMEM);
    cudaFuncSetAttribute(attn_mma_kernel, cudaFuncAttributeMaxDynamicSharedMemorySize, ATTN_SMEM);

    const bool out_holds_logits = ((long long)out_size >= (long long)MM * VV);
    float* logits = out_holds_logits ? (float*)d_out : lg_scratch;
    float* loss_ptr = out_holds_logits ? ((float*)d_out + (size_t)MM * VV)
                                       : (float*)d_out;
    const bool do_loss = (!out_holds_logits || (long long)out_size > (long long)MM * VV);

    convert_all_kernel<<<dim3(2304, 48), 256>>>(Wq, Wk, Wv, Wo, W1, W2);
    convert_tok_kernel<<<dim3(EE / 32, VV / 32), dim3(32, 32)>>>(tok, tok2);
    {
        size_t n = (size_t)MM * EE;
        embed_kernel<<<(unsigned)((n + 255) / 256), 256>>>(idx, tok, pos, x);
    }
    if (do_loss) loss_zero_kernel<<<1, 1>>>(loss_ptr);

    const int MAXCTA = 304;   // 2 CTAs/SM x 152 SMs (GB300)
    auto pgrid = [&](int N) { int t = (MM / 128) * (N / 128); return t < MAXCTA ? t : MAXCTA; };
    const int gQKV = pgrid(E3);
    const int gEc  = pgrid(EE);
    const int gFc  = pgrid(FF);
    const int gVc  = pgrid(VV);
    const int LN_GRID = MM / 8;

    for (int l = 0; l < LL; l++) {
        ln_split_kernel<<<LN_GRID, 256>>>(x, ln1_g + (size_t)l * EE, ln1_b + (size_t)l * EE, xn2);
        mma_gemm<1, false><<<gQKV, 256, GEMM_SMEM>>>(xn2, wqkv2 + (size_t)l * E2 * E3,
                                                     nullptr, nullptr, qkv2, MM, E3, E2, E2);
        attn_mma_kernel<<<dim3(TT / 128, HH, BB), 256, ATTN_SMEM>>>(qkv2, att2);
        mma_gemm<0, false><<<gEc, 256, GEMM_SMEM>>>(att2, wo2 + (size_t)l * E2 * EE,
                                                    bo + (size_t)l * EE, x, x, MM, EE, E2, E2);
        ln_split_kernel<<<LN_GRID, 256>>>(x, ln2_g + (size_t)l * EE, ln2_b + (size_t)l * EE, xn2);
        // h4 = round(gelu(xn @ W1 + b1))  (single fp16)
        mma_gemm<2, true><<<gFc, 256, GEMM_SMEM>>>(xn2, w12 + (size_t)l * E2 * FF,
                                                   b1 + (size_t)l * FF, nullptr, h42, MM, FF, E2, E2);
        // x = x + h4 @ W2 + b2  (1-term A, K=3072)
        mma_gemm<0, false><<<gEc, 256, GEMM_SMEM>>>(h42, w22 + (size_t)l * FF * EE,
                                                    b2 + (size_t)l * EE, x, x, MM, EE, FF, FF);
    }

    ln_split_kernel<<<LN_GRID, 256>>>(x, lnf_g, lnf_b, xn2);
    // lm-head: 1-term A (hi segment of xn2, pitch E2), 1-term B
    mma_gemm<0, false><<<gVc, 256, GEMM_SMEM>>>(xn2, tok2, nullptr, nullptr,
                                                logits, MM, VV, EE, E2);

    if (do_loss) loss_kernel<<<MM, 256>>>(logits, targets, loss_ptr);
}

// round 16
// speedup vs baseline: 2.1871x; 1.1223x over previous
#include <cuda_runtime.h>
#include <cuda_fp16.h>
#include <math.h>
#include <stdint.h>

// ---------------- problem constants ----------------
#define BB 4
#define TT 1024
#define EE 768
#define HH 8
#define HS 96
#define LL 8
#define VV 32000
#define FF 3072            // 4*E
#define MM (BB*TT)         // 4096 rows
#define E2 (2*EE)          // 1536 (2-term split K for E)
#define E3 (3*EE)          // 2304 (QKV output width q|k|v)

typedef __half fp16;

// ---------------- scratch (device globals; no allocation allowed) ----------------
__device__ __align__(256) float g_x   [(size_t)MM*EE];
__device__ __align__(256) fp16  g_xn2 [(size_t)MM*E2];         // ln out: pitch E2 (2-term) or EE (1-term)
__device__ __align__(256) fp16  g_qkv [(size_t)MM*E3];         // 1-term qkv
__device__ __align__(256) fp16  g_att2[(size_t)MM*E2];         // 2-term attention out
__device__ __align__(256) fp16  g_h42 [(size_t)MM*FF];         // 1-term h4

// weights: wqkv single [EE][E3]; wo/w1 duplicated [2K][N]; w2 single [FF][EE]; tok single [EE][VV]
__device__ __align__(256) fp16  g_wqkv2[(size_t)LL*EE*E3];
__device__ __align__(256) fp16  g_wo2  [(size_t)LL*E2*EE];
__device__ __align__(256) fp16  g_w12  [(size_t)LL*E2*FF];
__device__ __align__(256) fp16  g_w22  [(size_t)LL*FF*EE];
__device__ __align__(256) fp16  g_tok2 [(size_t)EE*VV];

__device__ __align__(256) float g_logits_scratch[(size_t)MM*VV];

// ---------------- helpers ----------------
__device__ __forceinline__ void split2h(float v, fp16& hi, fp16& lo) {
    hi = __float2half(v);
    lo = __float2half(v - __half2float(hi));
}
__device__ __forceinline__ uint32_t pack2h(fp16 a, fp16 b) {
    uint16_t x = *(uint16_t*)&a, y = *(uint16_t*)&b;
    return (uint32_t)x | ((uint32_t)y << 16);
}
__device__ __forceinline__ void cp16(void* dst_smem, const void* src_gmem) {
    uint32_t s = (uint32_t)__cvta_generic_to_shared(dst_smem);
    asm volatile("cp.async.cg.shared.global [%0], [%1], 16;\n" :: "r"(s), "l"(src_gmem));
}
__device__ __forceinline__ void cp_commit() { asm volatile("cp.async.commit_group;\n" ::: "memory"); }
__device__ __forceinline__ void cp_wait1()  { asm volatile("cp.async.wait_group 1;\n" ::: "memory"); }

__device__ __forceinline__ void ldmA4(uint32_t* a, const void* p) {
    uint32_t s = (uint32_t)__cvta_generic_to_shared(p);
    asm volatile("ldmatrix.sync.aligned.m8n8.x4.shared.b16 {%0,%1,%2,%3}, [%4];"
                 : "=r"(a[0]), "=r"(a[1]), "=r"(a[2]), "=r"(a[3]) : "r"(s));
}
__device__ __forceinline__ void ldmB4t(uint32_t* b, const void* p) {
    uint32_t s = (uint32_t)__cvta_generic_to_shared(p);
    asm volatile("ldmatrix.sync.aligned.m8n8.x4.trans.shared.b16 {%0,%1,%2,%3}, [%4];"
                 : "=r"(b[0]), "=r"(b[1]), "=r"(b[2]), "=r"(b[3]) : "r"(s));
}
__device__ __forceinline__ void mma16816h(float* c, const uint32_t* a, const uint32_t* b) {
    asm volatile(
        "mma.sync.aligned.m16n8k16.row.col.f32.f16.f16.f32 "
        "{%0,%1,%2,%3},{%4,%5,%6,%7},{%8,%9},{%0,%1,%2,%3};"
        : "+f"(c[0]), "+f"(c[1]), "+f"(c[2]), "+f"(c[3])
        : "r"(a[0]), "r"(a[1]), "r"(a[2]), "r"(a[3]), "r"(b[0]), "r"(b[1]));
}

// ---------------- batched weight conversion (vectorized x4) -------------
// segs 0-2 (QKV): single [K][N]. segs 3-4 (Wo,W1): dup [2K][N]. seg 5 (W2): single.
__global__ void convert_all_kernel(const float* __restrict__ Wq, const float* __restrict__ Wk,
                                   const float* __restrict__ Wv, const float* __restrict__ Wo,
                                   const float* __restrict__ W1, const float* __restrict__ W2)
{
    const int l = blockIdx.y / 6, seg = blockIdx.y % 6;
    const float* W; fp16* out; int K, N, pitch, colOff; bool dup;
    switch (seg) {
        case 0: W = Wq + (size_t)l*EE*EE; out = g_wqkv2 + (size_t)l*EE*E3; K=EE; N=EE; pitch=E3; colOff=0;    dup=false; break;
        case 1: W = Wk + (size_t)l*EE*EE; out = g_wqkv2 + (size_t)l*EE*E3; K=EE; N=EE; pitch=E3; colOff=EE;   dup=false; break;
        case 2: W = Wv + (size_t)l*EE*EE; out = g_wqkv2 + (size_t)l*EE*E3; K=EE; N=EE; pitch=E3; colOff=2*EE; dup=false; break;
        case 3: W = Wo + (size_t)l*EE*EE; out = g_wo2   + (size_t)l*E2*EE; K=EE; N=EE; pitch=EE; colOff=0;    dup=true;  break;
        case 4: W = W1 + (size_t)l*EE*FF; out = g_w12   + (size_t)l*E2*FF; K=EE; N=FF; pitch=FF; colOff=0;    dup=true;  break;
        default:W = W2 + (size_t)l*FF*EE; out = g_w22   + (size_t)l*FF*EE; K=FF; N=EE; pitch=EE; colOff=0;    dup=false; break;
    }
    int base = (blockIdx.x * 256 + threadIdx.x) * 4;
    if (base >= K * N) return;
    int k = base / N, n = base % N;
    float4 f = *(const float4*)&W[base];
    uint2 h;
    h.x = pack2h(__float2half(f.x), __float2half(f.y));
    h.y = pack2h(__float2half(f.z), __float2half(f.w));
    *(uint2*)&out[(size_t)k * pitch + colOff + n] = h;
    if (dup)
        *(uint2*)&out[(size_t)(K + k) * pitch + colOff + n] = h;
}

// Error contract: Wo/W1 GEMMs keep exact 2-term A (residual backbone = B-rounding only);
// QKV, W2, lm-head are 1-term (each adds one ~2.8e-4 quadrature source; measured non-compounding).

// ---------------- tok transpose: out[EE, V] from tok[V, E] (1-term B) -------------
__global__ void convert_tok_kernel(const float* __restrict__ tok, fp16* __restrict__ out)
{
    __shared__ float t[32][33];
    int k0 = blockIdx.x * 32, n0 = blockIdx.y * 32;
    int tx = threadIdx.x, ty = threadIdx.y;
    t[ty][tx] = tok[(size_t)(n0 + ty) * EE + k0 + tx];
    __syncthreads();
    fp16 hi = __float2half(t[tx][ty]);
    size_t k = k0 + ty, n = n0 + tx;
    out[k * VV + n] = hi;
}

// ---------------- embedding ----------------
__global__ void embed_kernel(const int* __restrict__ idx,
                             const float* __restrict__ tok,
                             const float* __restrict__ pos,
                             float* __restrict__ x)
{
    size_t i = (size_t)blockIdx.x * blockDim.x + threadIdx.x;
    if (i >= (size_t)MM * EE) return;
    int e  = (int)(i % EE);
    int bt = (int)(i / EE);
    int t  = bt % TT;
    x[i] = tok[(size_t)idx[bt] * EE + e] + pos[(size_t)t * EE + e];
}

// ---------------- layernorm, warp-per-row ----------------
// TWO=true: [hi | lo] pitch E2.  TWO=false: single hi, pitch EE.
template<bool TWO>
__global__ void ln_split_kernel(const float* __restrict__ x,
                                const float* __restrict__ g,
                                const float* __restrict__ b,
                                fp16* __restrict__ out)
{
    const int warp = threadIdx.x >> 5, lane = threadIdx.x & 31;
    const int row = blockIdx.x * 8 + warp;
    const float* xr = x + (size_t)row * EE;

    float4 v[6];
    float s = 0.f, s2 = 0.f;
#pragma unroll
    for (int j = 0; j < 6; j++) {
        v[j] = *(const float4*)&xr[(j * 32 + lane) * 4];
        s  += v[j].x + v[j].y + v[j].z + v[j].w;
        s2 += v[j].x * v[j].x + v[j].y * v[j].y + v[j].z * v[j].z + v[j].w * v[j].w;
    }
#pragma unroll
    for (int o = 16; o > 0; o >>= 1) {
        s  += __shfl_xor_sync(0xffffffffu, s,  o);
        s2 += __shfl_xor_sync(0xffffffffu, s2, o);
    }
    const float mean = s * (1.f / EE);
    const float var  = s2 * (1.f / EE) - mean * mean;
    const float inv  = rsqrtf(var + 1e-5f);

    fp16* orow = out + (size_t)row * (TWO ? E2 : EE);
#pragma unroll
    for (int j = 0; j < 6; j++) {
        const int e0 = (j * 32 + lane) * 4;
        float4 gg = *(const float4*)&g[e0];
        float4 bb = *(const float4*)&b[e0];
        float f0 = (v[j].x - mean) * inv * gg.x + bb.x;
        float f1 = (v[j].y - mean) * inv * gg.y + bb.y;
        float f2 = (v[j].z - mean) * inv * gg.z + bb.z;
        float f3 = (v[j].w - mean) * inv * gg.w + bb.w;
        if (TWO) {
            fp16 h0, l0, h1, l1, h2, l2, h3, l3;
            split2h(f0, h0, l0); split2h(f1, h1, l1);
            split2h(f2, h2, l2); split2h(f3, h3, l3);
            uint2 hv; hv.x = pack2h(h0, h1); hv.y = pack2h(h2, h3);
            uint2 lv; lv.x = pack2h(l0, l1); lv.y = pack2h(l2, l3);
            *(uint2*)&orow[e0]      = hv;
            *(uint2*)&orow[EE + e0] = lv;
        } else {
            uint2 hv;
            hv.x = pack2h(__float2half(f0), __float2half(f1));
            hv.y = pack2h(__float2half(f2), __float2half(f3));
            *(uint2*)&orow[e0] = hv;
        }
    }
}

// ---------------- tensor-core GEMM: C[M,N] = A[M,K2] @ B[K2,N] (fp16, fp32 acc) --------
// OUTMODE: 0 = fp32 (+res), 1 = split fp16 [hi|lo] pitch 2N, 2 = single fp16 pitch N.
template<int OUTMODE, bool GELU>
__global__ void __launch_bounds__(256, 2)
mma_gemm(const fp16* __restrict__ A, const fp16* __restrict__ B,
         const float* __restrict__ bias, const float* __restrict__ res,
         void* __restrict__ Cv, int M, int N, int K2, int lda)
{
    extern __shared__ char dynsm[];
    fp16* As = (fp16*)dynsm;             // [2][128*72]
    fp16* Bs = (fp16*)dynsm + 18432;     // [2][64*144]

    const int tid  = threadIdx.x;
    const int lane = tid & 31;
    const int warp = tid >> 5;
    const int wm   = warp & 1;
    const int wn   = warp >> 1;

    const int nRowT = M >> 7;
    const int nColT = N >> 7;
    const int nTiles = nRowT * nColT;
    const int ntk = K2 >> 6;

    for (int tile = blockIdx.x; tile < nTiles; tile += gridDim.x) {
        const int col0 = (tile / nRowT) * 128;
        const int row0 = (tile % nRowT) * 128;

        float acc[4][4][4];
#pragma unroll
        for (int i = 0; i < 4; i++)
#pragma unroll
            for (int j = 0; j < 4; j++)
#pragma unroll
                for (int r = 0; r < 4; r++) acc[i][j][r] = 0.f;

        auto load_tile = [&](int s, int k0) {
#pragma unroll
            for (int i = 0; i < 4; i++) {
                int idx = tid + i * 256;
                int r = idx >> 3, c = (idx & 7) * 8;
                cp16(&As[s * 9216 + r * 72 + c], &A[(size_t)(row0 + r) * lda + k0 + c]);
            }
#pragma unroll
            for (int i = 0; i < 4; i++) {
                int idx = tid + i * 256;
                int r = idx >> 4, c = (idx & 15) * 8;
                cp16(&Bs[s * 9216 + r * 144 + c], &B[(size_t)(k0 + r) * N + col0 + c]);
            }
        };

        __syncthreads();
        load_tile(0, 0);
        cp_commit();

        for (int t = 0; t < ntk; t++) {
            if (t + 1 < ntk) load_tile((t + 1) & 1, (t + 1) * 64);
            cp_commit();
            cp_wait1();
            __syncthreads();
            const int s = t & 1;

#pragma unroll
            for (int kk = 0; kk < 64; kk += 16) {
                uint32_t a[4][4], b[2][4];
#pragma unroll
                for (int mi = 0; mi < 4; mi++)
                    ldmA4(a[mi], &As[s * 9216 + (wm * 64 + mi * 16 + (lane & 15)) * 72 + kk + (lane >> 4) * 8]);
#pragma unroll
                for (int nj = 0; nj < 2; nj++)
                    ldmB4t(b[nj], &Bs[s * 9216 + (kk + (lane & 15)) * 144 + wn * 32 + nj * 16 + (lane >> 4) * 8]);
#pragma unroll
                for (int mi = 0; mi < 4; mi++) {
                    mma16816h(acc[mi][0], a[mi], b[0]);
                    mma16816h(acc[mi][1], a[mi], b[0] + 2);
                    mma16816h(acc[mi][2], a[mi], b[1]);
                    mma16816h(acc[mi][3], a[mi], b[1] + 2);
                }
            }
            __syncthreads();
        }

        // ---- epilogue ----
        const int gid = lane >> 2, tig = lane & 3;
#pragma unroll
        for (int mi = 0; mi < 4; mi++) {
#pragma unroll
            for (int ni = 0; ni < 4; ni++) {
                int gr = row0 + wm * 64 + mi * 16 + gid;
                int gc = col0 + wn * 32 + ni * 8 + tig * 2;
#pragma unroll
                for (int half = 0; half < 2; half++) {
                    int r = gr + half * 8;
#pragma unroll
                    for (int cc = 0; cc < 2; cc++) {
                        float c = acc[mi][ni][half * 2 + cc];
                        int col = gc + cc;
                        if (bias) c += bias[col];
                        if (GELU) c = 0.5f * c * (1.f + erff(c * 0.70710678118654752f));
                        if (OUTMODE == 1) {
                            fp16 hi, lo; split2h(c, hi, lo);
                            fp16* C = (fp16*)Cv;
                            size_t base = (size_t)r * (2 * N) + col;
                            C[base] = hi; C[base + N] = lo;
                        } else if (OUTMODE == 2) {
                            fp16* C = (fp16*)Cv;
                            C[(size_t)r * N + col] = __float2half(c);
                        } else {
                            float* C = (float*)Cv;
                            if (res) c += res[(size_t)r * N + col];
                            C[(size_t)r * N + col] = c;
                        }
                    }
                }
            }
        }
    }
}

// ---------------- fp16 flash attention (1-term q/k/v) ----------------
// qkv: [M][E3] fp16 (q|k|v). att2: [M][2*EE] = [hi | lo].
// Smem: Qs[128][104] @0 (26624), Ks[96][72] @26624 (13824),
//       Vs[64][104] @40448 (13312), Ps[128][72] @53760 (18432). Total 72192.
__global__ void __launch_bounds__(256)
attn_mma_kernel(const fp16* __restrict__ qkv, fp16* __restrict__ att2)
{
    extern __shared__ char dynsm[];
    fp16* Qs = (fp16*)dynsm;
    fp16* Ks = (fp16*)(dynsm + 26624);
    fp16* Vs = (fp16*)(dynsm + 40448);
    fp16* Ps = (fp16*)(dynsm + 53760);

    const int qb0  = blockIdx.x * 128;
    const int h    = blockIdx.y;
    const int b    = blockIdx.z;
    const int tid  = threadIdx.x;
    const int lane = tid & 31;
    const int w    = tid >> 5;
    const int gid  = lane >> 2, tig = lane & 3;

    const size_t NQ = E3;
    const size_t rowbase = (size_t)(b * TT) * NQ;
    const int qoff = h * HS, koff = EE + h * HS, voff = 2 * EE + h * HS;

    for (int i = tid; i < 128 * 12; i += 256) {
        int r = i / 12, e0 = (i % 12) * 8;
        *(uint4*)&Qs[r * 104 + e0] = *(const uint4*)&qkv[rowbase + (size_t)(qb0 + r) * NQ + qoff + e0];
    }

    float o[12][4];
#pragma unroll
    for (int i = 0; i < 12; i++)
#pragma unroll
        for (int j = 0; j < 4; j++) o[i][j] = 0.f;
    float mrow0 = -1e30f, mrow1 = -1e30f, lrow0 = 0.f, lrow1 = 0.f;

    const float scale = 0.10206207261596577f;
    const int nchunks = qb0 / 64 + 2;

    for (int ch = 0; ch < nchunks; ch++) {
        const int c0 = ch * 64;
        __syncthreads();
        for (int i = tid; i < 64 * 12; i += 256) {
            int key = i / 12, e0 = (i % 12) * 8;
            const size_t g = rowbase + (size_t)(c0 + key) * NQ;
            uint4 khiv = *(const uint4*)&qkv[g + koff + e0];
            const fp16* kh = (const fp16*)&khiv;
#pragma unroll
            for (int j = 0; j < 8; j++)
                Ks[(e0 + j) * 72 + key] = kh[j];
            *(uint4*)&Vs[key * 104 + e0] = *(const uint4*)&qkv[g + voff + e0];
        }
        __syncthreads();

        // ---- S = Q K^T (single segment) ----
        float sacc[8][4];
#pragma unroll
        for (int i = 0; i < 8; i++)
#pragma unroll
            for (int j = 0; j < 4; j++) sacc[i][j] = 0.f;

#pragma unroll
        for (int kk = 0; kk < 96; kk += 16) {
            uint32_t a[4];
            ldmA4(a, &Qs[(w * 16 + (lane & 15)) * 104 + kk + (lane >> 4) * 8]);
#pragma unroll
            for (int nt = 0; nt < 8; nt += 2) {
                uint32_t bb[4];
                ldmB4t(bb, &Ks[(kk + (lane & 15)) * 72 + nt * 8 + (lane >> 4) * 8]);
                mma16816h(sacc[nt],     a, bb);
                mma16816h(sacc[nt + 1], a, bb + 2);
            }
        }

        const int rg0 = qb0 + w * 16 + gid;
        const bool need_mask = (c0 + 64 > qb0);
        float cm0 = -1e30f, cm1 = -1e30f;
#pragma unroll
        for (int nt = 0; nt < 8; nt++) {
#pragma unroll
            for (int e = 0; e < 4; e++) {
                float s = sacc[nt][e] * scale;
                if (need_mask) {
                    int col = c0 + nt * 8 + tig * 2 + (e & 1);
                    int row = rg0 + (e >> 1) * 8;
                    if (col > row) s = -1e30f;
                }
                sacc[nt][e] = s;
                if (e < 2) cm0 = fmaxf(cm0, s); else cm1 = fmaxf(cm1, s);
            }
        }
        cm0 = fmaxf(cm0, __shfl_xor_sync(0xffffffffu, cm0, 1));
        cm0 = fmaxf(cm0, __shfl_xor_sync(0xffffffffu, cm0, 2));
        cm1 = fmaxf(cm1, __shfl_xor_sync(0xffffffffu, cm1, 1));
        cm1 = fmaxf(cm1, __shfl_xor_sync(0xffffffffu, cm1, 2));

        const float mn0 = fmaxf(mrow0, cm0), mn1 = fmaxf(mrow1, cm1);
        const float al0 = __expf(mrow0 - mn0), al1 = __expf(mrow1 - mn1);
        float cs0 = 0.f, cs1 = 0.f;
#pragma unroll
        for (int nt = 0; nt < 8; nt++) {
            float p0 = __expf(sacc[nt][0] - mn0), p1 = __expf(sacc[nt][1] - mn0);
            float p2 = __expf(sacc[nt][2] - mn1), p3 = __expf(sacc[nt][3] - mn1);
            cs0 += p0 + p1; cs1 += p2 + p3;
            int colb = nt * 8 + tig * 2;
            *(uint32_t*)&Ps[(w * 16 + gid) * 72 + colb]     = pack2h(__float2half(p0), __float2half(p1));
            *(uint32_t*)&Ps[(w * 16 + gid + 8) * 72 + colb] = pack2h(__float2half(p2), __float2half(p3));
        }
        cs0 += __shfl_xor_sync(0xffffffffu, cs0, 1);
        cs0 += __shfl_xor_sync(0xffffffffu, cs0, 2);
        cs1 += __shfl_xor_sync(0xffffffffu, cs1, 1);
        cs1 += __shfl_xor_sync(0xffffffffu, cs1, 2);

        lrow0 = lrow0 * al0 + cs0; lrow1 = lrow1 * al1 + cs1;
        mrow0 = mn0; mrow1 = mn1;
#pragma unroll
        for (int nt = 0; nt < 12; nt++) {
            o[nt][0] *= al0; o[nt][1] *= al0; o[nt][2] *= al1; o[nt][3] *= al1;
        }
        __syncwarp();

#pragma unroll
        for (int kk = 0; kk < 64; kk += 16) {
            uint32_t a[4];
            ldmA4(a, &Ps[(w * 16 + (lane & 15)) * 72 + kk + (lane >> 4) * 8]);
#pragma unroll
            for (int nt = 0; nt < 12; nt += 2) {
                uint32_t bb[4];
                ldmB4t(bb, &Vs[(kk + (lane & 15)) * 104 + nt * 8 + (lane >> 4) * 8]);
                mma16816h(o[nt],     a, bb);
                mma16816h(o[nt + 1], a, bb + 2);
            }
        }
    }

    const float iv0 = 1.f / lrow0, iv1 = 1.f / lrow1;
#pragma unroll
    for (int nt = 0; nt < 12; nt++) {
        int d = h * HS + nt * 8 + tig * 2;
        {
            size_t orow = (size_t)(b * TT + qb0 + w * 16 + gid) * E2;
            float v0 = o[nt][0] * iv0, v1 = o[nt][1] * iv0;
            fp16 h0, l0, h1, l1; split2h(v0, h0, l0); split2h(v1, h1, l1);
            *(uint32_t*)&att2[orow + d]      = pack2h(h0, h1);
            *(uint32_t*)&att2[orow + EE + d] = pack2h(l0, l1);
        }
        {
            size_t orow = (size_t)(b * TT + qb0 + w * 16 + gid + 8) * E2;
            float v0 = o[nt][2] * iv1, v1 = o[nt][3] * iv1;
            fp16 h0, l0, h1, l1; split2h(v0, h0, l0); split2h(v1, h1, l1);
            *(uint32_t*)&att2[orow + d]      = pack2h(h0, h1);
            *(uint32_t*)&att2[orow + EE + d] = pack2h(l0, l1);
        }
    }
}

// ---------------- loss (single pass, online logsumexp, float4 reads) ---------------
__global__ void loss_zero_kernel(float* loss) { *loss = 0.f; }

__global__ void loss_kernel(const float* __restrict__ logits,
                            const int* __restrict__ targets,
                            float* __restrict__ loss)
{
    const int row = blockIdx.x;
    const int tid = threadIdx.x;   // 256
    const float* lr = logits + (size_t)row * VV;

    float m = -1e30f, s = 0.f;
    for (int j4 = tid; j4 < VV / 4; j4 += 256) {
        float4 f = *(const float4*)&lr[j4 * 4];
        float vals[4] = {f.x, f.y, f.z, f.w};
#pragma unroll
        for (int q = 0; q < 4; q++) {
            float v = vals[q];
            if (v > m) { s = s * __expf(m - v) + 1.f; m = v; }
            else       { s += __expf(v - m); }
        }
    }
    __shared__ float rm[256], rs[256];
    rm[tid] = m; rs[tid] = s; __syncthreads();
    for (int o = 128; o > 0; o >>= 1) {
        if (tid < o) {
            float m2 = rm[tid + o], s2 = rs[tid + o];
            float mm = fmaxf(rm[tid], m2);
            rs[tid] = rs[tid] * __expf(rm[tid] - mm) + s2 * __expf(m2 - mm);
            rm[tid] = mm;
        }
        __syncthreads();
    }
    if (tid == 0) {
        float lp = lr[targets[row]] - rm[0] - logf(rs[0]);
        atomicAdd(loss, -lp * (1.f / (float)MM));
    }
}

// ---------------- launch ----------------
extern "C" void kernel_launch(void* const* d_in, const int* in_sizes, int n_in,
                              void* d_out, int out_size)
{
    const int*   idx     = (const int*)  d_in[0];
    const int*   targets = (const int*)  d_in[1];
    const float* tok     = (const float*)d_in[2];
    const float* pos     = (const float*)d_in[3];
    const float* Wq      = (const float*)d_in[4];
    const float* Wk      = (const float*)d_in[5];
    const float* Wv      = (const float*)d_in[6];
    const float* Wo      = (const float*)d_in[7];
    const float* bo      = (const float*)d_in[8];
    const float* ln1_g   = (const float*)d_in[9];
    const float* ln1_b   = (const float*)d_in[10];
    const float* ln2_g   = (const float*)d_in[11];
    const float* ln2_b   = (const float*)d_in[12];
    const float* W1      = (const float*)d_in[13];
    const float* b1      = (const float*)d_in[14];
    const float* W2      = (const float*)d_in[15];
    const float* b2      = (const float*)d_in[16];
    const float* lnf_g   = (const float*)d_in[17];
    const float* lnf_b   = (const float*)d_in[18];

    float *x, *lg_scratch;
    fp16 *xn2, *qkv, *att2, *h42, *wqkv2, *wo2, *w12, *w22, *tok2;
    cudaGetSymbolAddress((void**)&x,    g_x);
    cudaGetSymbolAddress((void**)&xn2,  g_xn2);
    cudaGetSymbolAddress((void**)&qkv,  g_qkv);
    cudaGetSymbolAddress((void**)&att2, g_att2);
    cudaGetSymbolAddress((void**)&h42,  g_h42);
    cudaGetSymbolAddress((void**)&wqkv2,g_wqkv2);
    cudaGetSymbolAddress((void**)&wo2,  g_wo2);
    cudaGetSymbolAddress((void**)&w12,  g_w12);
    cudaGetSymbolAddress((void**)&w22,  g_w22);
    cudaGetSymbolAddress((void**)&tok2, g_tok2);
    cudaGetSymbolAddress((void**)&lg_scratch, g_logits_scratch);

    const int GEMM_SMEM = 73728;
    const int ATTN_SMEM = 72192;
    cudaFuncSetAttribute(mma_gemm<1,false>, cudaFuncAttributeMaxDynamicSharedMemorySize, GEMM_SMEM);
    cudaFuncSetAttribute(mma_gemm<2,false>, cudaFuncAttributeMaxDynamicSharedMemorySize, GEMM_SMEM);
    cudaFuncSetAttribute(mma_gemm<2,true >, cudaFuncAttributeMaxDynamicSharedMemorySize, GEMM_SMEM);
    cudaFuncSetAttribute(mma_gemm<0,false>, cudaFuncAttributeMaxDynamicSharedMemorySize, GEMM_SMEM);
    cudaFuncSetAttribute(attn_mma_kernel, cudaFuncAttributeMaxDynamicSharedMemorySize, ATTN_SMEM);

    const bool out_holds_logits = ((long long)out_size >= (long long)MM * VV);
    float* logits = out_holds_logits ? (float*)d_out : lg_scratch;
    float* loss_ptr = out_holds_logits ? ((float*)d_out + (size_t)MM * VV)
                                       : (float*)d_out;
    const bool do_loss = (!out_holds_logits || (long long)out_size > (long long)MM * VV);

    convert_all_kernel<<<dim3(2304, 48), 256>>>(Wq, Wk, Wv, Wo, W1, W2);
    convert_tok_kernel<<<dim3(EE / 32, VV / 32), dim3(32, 32)>>>(tok, tok2);
    {
        size_t n = (size_t)MM * EE;
        embed_kernel<<<(unsigned)((n + 255) / 256), 256>>>(idx, tok, pos, x);
    }
    if (do_loss) loss_zero_kernel<<<1, 1>>>(loss_ptr);

    const int MAXCTA = 304;   // 2 CTAs/SM x 152 SMs
    auto pgrid = [&](int N) { int t = (MM / 128) * (N / 128); return t < MAXCTA ? t : MAXCTA; };
    const int gQKV = pgrid(E3);
    const int gEc  = pgrid(EE);
    const int gFc  = pgrid(FF);
    const int gVc  = pgrid(VV);
    const int LN_GRID = MM / 8;

    for (int l = 0; l < LL; l++) {
        // ln1 -> 1-term (pitch EE); qkv = xn1 @ Wqkv (1-term, K=768)
        ln_split_kernel<false><<<LN_GRID, 256>>>(x, ln1_g + (size_t)l * EE, ln1_b + (size_t)l * EE, xn2);
        mma_gemm<2, false><<<gQKV, 256, GEMM_SMEM>>>(xn2, wqkv2 + (size_t)l * EE * E3,
                                                     nullptr, nullptr, qkv, MM, E3, EE, EE);
        attn_mma_kernel<<<dim3(TT / 128, HH, BB), 256, ATTN_SMEM>>>(qkv, att2);
        // x = x + att @ Wo + bo  (2-term A)
        mma_gemm<0, false><<<gEc, 256, GEMM_SMEM>>>(att2, wo2 + (size_t)l * E2 * EE,
                                                    bo + (size_t)l * EE, x, x, MM, EE, E2, E2);
        // ln2 -> 2-term; h4 = round(gelu(xn @ W1 + b1))
        ln_split_kernel<true><<<LN_GRID, 256>>>(x, ln2_g + (size_t)l * EE, ln2_b + (size_t)l * EE, xn2);
        mma_gemm<2, true><<<gFc, 256, GEMM_SMEM>>>(xn2, w12 + (size_t)l * E2 * FF,
                                                   b1 + (size_t)l * FF, nullptr, h42, MM, FF, E2, E2);
        // x = x + h4 @ W2 + b2  (1-term A, K=3072)
        mma_gemm<0, false><<<gEc, 256, GEMM_SMEM>>>(h42, w22 + (size_t)l * FF * EE,
                                                    b2 + (size_t)l * EE, x, x, MM, EE, FF, FF);
    }

    // lnf -> 1-term; lm-head 1-term A/B
    ln_split_kernel<false><<<LN_GRID, 256>>>(x, lnf_g, lnf_b, xn2);
    mma_gemm<0, false><<<gVc, 256, GEMM_SMEM>>>(xn2, tok2, nullptr, nullptr,
                                                logits, MM, VV, EE, EE);

    if (do_loss) loss_kernel<<<MM, 256>>>(logits, targets, loss_ptr);
}